// round 7
// baseline (speedup 1.0000x reference)
#include <cuda_runtime.h>
#include <math.h>

#define B 8
#define S 2048
#define D 128
#define H 4
#define DK 32
#define RT (B*S)          // 16384 rows
#define EPS 1e-5f

// TF32 rounding (emulates XLA/cuBLAS TF32 dot inputs)
__device__ __forceinline__ float tf32r(float x) {
    float y;
    asm("cvt.rna.tf32.f32 %0, %1;" : "=f"(y) : "f"(x));
    return y;
}

// ---------------- scratch (static __device__ globals; no allocation) ----------------
__device__ float g_resid[RT * D];                 // [B*S, D]
__device__ float g_Q[RT * D];                     // [B,H,S,DK]
__device__ float g_K[RT * D];                     // [B,H,S,DK]
__device__ float g_V[RT * D];                     // [B,H,S,DK]
__device__ float g_ctx[RT * D];                   // [B,S,H*DK]
__device__ float g_scores[134217728];             // [B,H,S,S] fallback if attn not in d_out
__device__ int   g_mask_mode;                     // 0 = 1-byte bool, 1 = 4-byte (int32/float32)

// ---------------- mask storage-width detection ----------------
// Byte-stored bool: ~50% of bytes at j%4==1 are nonzero over 8192 bytes.
// int32 (0x00000001) / float32 (0x3F800000) widened bool: byte j%4==1 is ALWAYS 0.
// Only reads first 8192 bytes -> in-bounds under every storage interpretation.
__global__ void detect_mask_kernel(const unsigned char* __restrict__ m) {
    __shared__ int found;
    if (threadIdx.x == 0) found = 0;
    __syncthreads();
    // positions j = 4*i + 1, i in [0, 2048)
    for (int i = threadIdx.x; i < 2048; i += blockDim.x)
        if (m[4 * i + 1] != 0) found = 1;   // benign race: any writer sets 1
    __syncthreads();
    if (threadIdx.x == 0) g_mask_mode = found ? 0 : 1;
}

// ---------------- projections: out = X @ W (TF32 inputs), optionally head-split ----------------
__global__ void proj_kernel(const float* __restrict__ X, const float* __restrict__ W,
                            float* __restrict__ out, int headSplit) {
    __shared__ float xs[16][128];
    const int rowBase = blockIdx.x * 16;
    const int c = threadIdx.x;                    // 0..127
    #pragma unroll
    for (int r = 0; r < 16; ++r)
        xs[r][c] = tf32r(X[(size_t)(rowBase + r) * D + c]);
    __syncthreads();

    float acc[16];
    #pragma unroll
    for (int r = 0; r < 16; ++r) acc[r] = 0.f;

    for (int k = 0; k < D; ++k) {
        float w = tf32r(W[k * D + c]);            // coalesced; W stays L2-resident
        #pragma unroll
        for (int r = 0; r < 16; ++r)
            acc[r] = fmaf(xs[r][k], w, acc[r]);   // xs[r][k]: warp-broadcast
    }

    if (!headSplit) {
        #pragma unroll
        for (int r = 0; r < 16; ++r)
            out[(size_t)(rowBase + r) * D + c] = acc[r];
    } else {
        const int h = c >> 5, d = c & 31;
        #pragma unroll
        for (int r = 0; r < 16; ++r) {
            const int row = rowBase + r;
            const int b = row / S, s = row % S;
            out[(((size_t)(b * H + h)) * S + s) * DK + d] = acc[r];
        }
    }
}

// ---------------- scores = Q K^T / sqrt(dk) (TF32 inputs), masked ----------------
__global__ void scores_kernel(const float* __restrict__ Q, const float* __restrict__ K,
                              const void* __restrict__ mask_raw,
                              float* __restrict__ sc) {
    const int kt = blockIdx.x, qt = blockIdx.y, bh = blockIdx.z;
    const int b = bh / H;
    __shared__ float qs[64][33];                  // padded vs bank conflicts
    __shared__ float ks[64][33];
    const int tid = threadIdx.x;
    const int mode = g_mask_mode;                 // 0 = byte, 1 = 4-byte

    const float* Qb = Q + ((size_t)bh * S + qt * 64) * DK;
    const float* Kb = K + ((size_t)bh * S + kt * 64) * DK;
    for (int i = tid; i < 64 * DK; i += 256) {
        qs[i / DK][i % DK] = tf32r(Qb[i]);
        ks[i / DK][i % DK] = tf32r(Kb[i]);
    }
    __syncthreads();

    const int tq = (tid >> 4) * 4;                // 0..60
    const int tk = (tid & 15) * 4;                // 0..60
    float acc[4][4] = {};
    for (int d = 0; d < DK; ++d) {
        float qv[4], kv[4];
        #pragma unroll
        for (int i = 0; i < 4; ++i) { qv[i] = qs[tq + i][d]; kv[i] = ks[tk + i][d]; }
        #pragma unroll
        for (int i = 0; i < 4; ++i)
            #pragma unroll
            for (int j = 0; j < 4; ++j)
                acc[i][j] = fmaf(qv[i], kv[j], acc[i][j]);
    }

    const float scale = 0.17677669529663687f;     // 1/sqrt(32)
    const size_t base = ((size_t)bh * S + (size_t)qt * 64) * S + (size_t)kt * 64;
    const unsigned char* m8  = (const unsigned char*)mask_raw;
    const unsigned int*  m32 = (const unsigned int*)mask_raw;
    #pragma unroll
    for (int i = 0; i < 4; ++i) {
        const int q = qt * 64 + tq + i;
        const size_t mbase = ((size_t)b * S + q) * S + (size_t)kt * 64;
        float* srow = sc + base + (size_t)(tq + i) * S;
        #pragma unroll
        for (int j = 0; j < 4; ++j) {
            const int k = tk + j;
            const bool masked = mode ? (m32[mbase + k] != 0u)
                                     : (m8 [mbase + k] != 0);
            srow[k] = masked ? -1e9f : acc[i][j] * scale;
        }
    }
}

// ---------------- row softmax in place (fp32 exact) ----------------
__global__ void softmax_kernel(float* __restrict__ sc) {
    float* p = sc + (size_t)blockIdx.x * S;
    const int tid = threadIdx.x;
    float vals[8];
    float m = -INFINITY;
    #pragma unroll
    for (int i = 0; i < 8; ++i) { vals[i] = p[tid + i * 256]; m = fmaxf(m, vals[i]); }

    __shared__ float red[256];
    red[tid] = m; __syncthreads();
    for (int s2 = 128; s2 > 0; s2 >>= 1) {
        if (tid < s2) red[tid] = fmaxf(red[tid], red[tid + s2]);
        __syncthreads();
    }
    m = red[0]; __syncthreads();

    float sum = 0.f;
    #pragma unroll
    for (int i = 0; i < 8; ++i) { vals[i] = expf(vals[i] - m); sum += vals[i]; }
    red[tid] = sum; __syncthreads();
    for (int s2 = 128; s2 > 0; s2 >>= 1) {
        if (tid < s2) red[tid] += red[tid + s2];
        __syncthreads();
    }
    const float inv = 1.0f / red[0];
    #pragma unroll
    for (int i = 0; i < 8; ++i) p[tid + i * 256] = vals[i] * inv;
}

// ---------------- context = attn @ V (TF32 inputs) ----------------
__global__ void pv_kernel(const float* __restrict__ sc, const float* __restrict__ V,
                          float* __restrict__ ctx) {
    const int qt = blockIdx.x, bh = blockIdx.y;
    const int b = bh / H, h = bh % H;
    __shared__ float as[64][64];                  // attn chunk
    __shared__ float vs[64][DK];                  // V chunk
    const int tid = threadIdx.x;
    const int d  = tid & 31;
    const int qg = tid >> 5;                      // 0..7
    float acc[8] = {};

    for (int kt = 0; kt < S; kt += 64) {
        const float* ab = sc + ((size_t)bh * S + (size_t)qt * 64) * S + kt;
        for (int i = tid; i < 64 * 64; i += 256)
            as[i >> 6][i & 63] = tf32r(ab[(size_t)(i >> 6) * S + (i & 63)]);
        const float* vb = V + ((size_t)bh * S + kt) * DK;
        for (int i = tid; i < 64 * DK; i += 256)
            vs[i >> 5][i & 31] = tf32r(vb[i]);
        __syncthreads();

        for (int kk = 0; kk < 64; ++kk) {
            float v = vs[kk][d];                  // conflict-free
            #pragma unroll
            for (int i = 0; i < 8; ++i)
                acc[i] = fmaf(as[qg + i * 8][kk], v, acc[i]);   // warp-broadcast
        }
        __syncthreads();
    }
    #pragma unroll
    for (int i = 0; i < 8; ++i) {
        const int s = qt * 64 + qg + i * 8;
        ctx[((size_t)b * S + s) * D + h * DK + d] = acc[i];
    }
}

// ---------------- final: y = ctx @ Wo (TF32) + resid; out = layernorm(y) ----------------
__global__ void out_kernel(const float* __restrict__ Wo, float* __restrict__ out) {
    __shared__ float xs[16][128];
    __shared__ float ys[16][129];                 // padded
    __shared__ float mu[16], rstd[16];
    const int rowBase = blockIdx.x * 16;
    const int c = threadIdx.x;

    #pragma unroll
    for (int r = 0; r < 16; ++r)
        xs[r][c] = tf32r(g_ctx[(size_t)(rowBase + r) * D + c]);
    __syncthreads();

    float acc[16];
    #pragma unroll
    for (int r = 0; r < 16; ++r)
        acc[r] = g_resid[(size_t)(rowBase + r) * D + c];
    for (int k = 0; k < D; ++k) {
        float w = tf32r(Wo[k * D + c]);
        #pragma unroll
        for (int r = 0; r < 16; ++r)
            acc[r] = fmaf(xs[r][k], w, acc[r]);
    }
    #pragma unroll
    for (int r = 0; r < 16; ++r) ys[r][c] = acc[r];
    __syncthreads();

    if (c < 16) {
        float s1 = 0.f, s2 = 0.f;
        for (int k = 0; k < D; ++k) { float v = ys[c][k]; s1 += v; s2 += v * v; }
        const float m = s1 * (1.0f / D);
        const float var = s2 * (1.0f / D) - m * m;
        mu[c] = m; rstd[c] = rsqrtf(var + EPS);
    }
    __syncthreads();
    #pragma unroll
    for (int r = 0; r < 16; ++r)
        out[(size_t)(rowBase + r) * D + c] = (ys[r][c] - mu[r]) * rstd[r];
}

// ---------------- launch ----------------
extern "C" void kernel_launch(void* const* d_in, const int* in_sizes, int n_in,
                              void* d_out, int out_size) {
    const float* inQ = (const float*)d_in[0];
    const float* inK = (const float*)d_in[1];
    const float* inV = (const float*)d_in[2];
    const void*  mask = d_in[3];                  // bool; storage width detected on device
    const float* W0 = (const float*)d_in[4];
    const float* Wq = (const float*)d_in[5];
    const float* Wk = (const float*)d_in[6];
    const float* Wv = (const float*)d_in[7];
    const float* Wo = (const float*)d_in[8];
    float* out = (float*)d_out;

    float *resid_p, *Q_p, *K_p, *V_p, *ctx_p, *sc_p;
    cudaGetSymbolAddress((void**)&resid_p, g_resid);
    cudaGetSymbolAddress((void**)&Q_p, g_Q);
    cudaGetSymbolAddress((void**)&K_p, g_K);
    cudaGetSymbolAddress((void**)&V_p, g_V);
    cudaGetSymbolAddress((void**)&ctx_p, g_ctx);
    cudaGetSymbolAddress((void**)&sc_p, g_scores);

    const size_t normElems = (size_t)RT * D;                 // 2,097,152
    const size_t attnElems = (size_t)B * H * S * S;          // 134,217,728
    float* sc = ((size_t)out_size >= normElems + attnElems) ? out + normElems : sc_p;

    // 0) detect mask storage width (bounded to first 8KB; always in-bounds)
    detect_mask_kernel<<<1, 256>>>((const unsigned char*)mask);

    // 1) projections
    proj_kernel<<<RT / 16, 128>>>(inQ, W0, resid_p, 0);
    proj_kernel<<<RT / 16, 128>>>(inQ, Wq, Q_p, 1);
    proj_kernel<<<RT / 16, 128>>>(inK, Wk, K_p, 1);
    proj_kernel<<<RT / 16, 128>>>(inV, Wv, V_p, 1);

    // 2) masked scores
    scores_kernel<<<dim3(S / 64, S / 64, B * H), 256>>>(Q_p, K_p, mask, sc);

    // 3) softmax (in place)
    softmax_kernel<<<B * H * S, 256>>>(sc);

    // 4) context = attn @ V
    pv_kernel<<<dim3(S / 64, B * H), 256>>>(sc, V_p, ctx_p);

    // 5) output proj + residual + layernorm
    out_kernel<<<RT / 16, 128>>>(Wo, out);
}

// round 8
// speedup vs baseline: 1.0387x; 1.0387x over previous
#include <cuda_runtime.h>
#include <math.h>

#define B 8
#define S 2048
#define D 128
#define H 4
#define DK 32
#define RT (B*S)          // 16384 rows
#define EPS 1e-5f

// ---------------- scratch (static __device__ globals; no allocation) ----------------
__device__ float g_resid[RT * D];                 // [B*S, D]
__device__ float g_Q[RT * D];                     // [B,H,S,DK]
__device__ float g_K[RT * D];                     // [B,H,S,DK]
__device__ float g_V[RT * D];                     // [B,H,S,DK]
__device__ float g_ctx[RT * D];                   // [B,S,H*DK]
__device__ float g_part[32 * 16 * S];             // per-(bh,ktile128,q) row-max partials
__device__ float g_rowmax[32 * S];                // per-(bh,q) row max
__device__ float g_scores[134217728];             // [B,H,S,S] fallback if attn not in d_out

// ---------------- projections: out = X @ W, optionally head-split ----------------
// 128 threads, 8 rows per block. Thread c owns output column c for 8 rows.
__global__ __launch_bounds__(128) void proj_kernel(
        const float* __restrict__ X, const float* __restrict__ W,
        float* __restrict__ out, int headSplit) {
    __shared__ float xs[8][128];
    const int rowBase = blockIdx.x * 8;
    const int c = threadIdx.x;                    // 0..127
    #pragma unroll
    for (int r = 0; r < 8; ++r)
        xs[r][c] = X[(size_t)(rowBase + r) * D + c];
    __syncthreads();

    float acc[8];
    #pragma unroll
    for (int r = 0; r < 8; ++r) acc[r] = 0.f;

    for (int k = 0; k < D; ++k) {
        float w = W[k * D + c];                   // coalesced; W stays L2-resident
        #pragma unroll
        for (int r = 0; r < 8; ++r)
            acc[r] = fmaf(xs[r][k], w, acc[r]);   // xs[r][k]: warp-broadcast
    }

    if (!headSplit) {
        #pragma unroll
        for (int r = 0; r < 8; ++r)
            out[(size_t)(rowBase + r) * D + c] = acc[r];
    } else {
        const int h = c >> 5, d = c & 31;
        #pragma unroll
        for (int r = 0; r < 8; ++r) {
            const int row = rowBase + r;
            const int b = row / S, s = row % S;
            out[(((size_t)(b * H + h)) * S + s) * DK + d] = acc[r];
        }
    }
}

// ---------------- scores = Q K^T / sqrt(dk), masked; emits per-row tile maxima --------
// grid (kt=16, qt=16, bh=32), 256 threads; 128x128 tile, 8x8 micro-tile.
__global__ __launch_bounds__(256, 2) void scores_kernel(
        const float* __restrict__ Q, const float* __restrict__ K,
        const int* __restrict__ mask, float* __restrict__ sc) {
    const int kt = blockIdx.x, qt = blockIdx.y, bh = blockIdx.z;
    const int b = bh >> 2;                        // bh = b*H + h
    __shared__ float qs[128][33];
    __shared__ float ks[128][33];
    const int tid = threadIdx.x;

    const float4* Qb = (const float4*)(Q + ((size_t)bh * S + (size_t)qt * 128) * DK);
    const float4* Kb = (const float4*)(K + ((size_t)bh * S + (size_t)kt * 128) * DK);
    for (int f = tid; f < 1024; f += 256) {       // 128 rows * 8 float4
        const int row = f >> 3, sg = (f & 7) * 4;
        float4 v = Qb[f];
        qs[row][sg] = v.x; qs[row][sg+1] = v.y; qs[row][sg+2] = v.z; qs[row][sg+3] = v.w;
        v = Kb[f];
        ks[row][sg] = v.x; ks[row][sg+1] = v.y; ks[row][sg+2] = v.z; ks[row][sg+3] = v.w;
    }
    __syncthreads();

    const int tk = (tid & 15) * 8;                // 0..120
    const int tq = (tid >> 4) * 8;                // 0..120
    float acc[8][8] = {};
    for (int d = 0; d < DK; ++d) {
        float qv[8], kv[8];
        #pragma unroll
        for (int i = 0; i < 8; ++i) { qv[i] = qs[tq + i][d]; kv[i] = ks[tk + i][d]; }
        #pragma unroll
        for (int i = 0; i < 8; ++i)
            #pragma unroll
            for (int j = 0; j < 8; ++j)
                acc[i][j] = fmaf(qv[i], kv[j], acc[i][j]);
    }

    const float scale = 0.17677669529663687f;     // 1/sqrt(32)
    float rmax[8];
    #pragma unroll
    for (int i = 0; i < 8; ++i) {
        const int q = qt * 128 + tq + i;
        const int4* mrow = (const int4*)(mask + ((size_t)b * S + q) * S + (size_t)kt * 128 + tk);
        float4* srow = (float4*)(sc + ((size_t)bh * S + q) * S + (size_t)kt * 128 + tk);
        const int4 m0 = mrow[0], m1 = mrow[1];
        float4 o0, o1;
        o0.x = m0.x ? -1e9f : acc[i][0] * scale;
        o0.y = m0.y ? -1e9f : acc[i][1] * scale;
        o0.z = m0.z ? -1e9f : acc[i][2] * scale;
        o0.w = m0.w ? -1e9f : acc[i][3] * scale;
        o1.x = m1.x ? -1e9f : acc[i][4] * scale;
        o1.y = m1.y ? -1e9f : acc[i][5] * scale;
        o1.z = m1.z ? -1e9f : acc[i][6] * scale;
        o1.w = m1.w ? -1e9f : acc[i][7] * scale;
        srow[0] = o0; srow[1] = o1;
        float mx = fmaxf(fmaxf(fmaxf(o0.x, o0.y), fmaxf(o0.z, o0.w)),
                         fmaxf(fmaxf(o1.x, o1.y), fmaxf(o1.z, o1.w)));
        rmax[i] = mx;
    }
    // reduce max across the 16 threads (same tq, different tk): lanes stay in 16-lane halves
    #pragma unroll
    for (int off = 1; off < 16; off <<= 1)
        #pragma unroll
        for (int i = 0; i < 8; ++i)
            rmax[i] = fmaxf(rmax[i], __shfl_xor_sync(0xffffffffu, rmax[i], off));
    if ((tid & 15) == 0) {
        #pragma unroll
        for (int i = 0; i < 8; ++i)
            g_part[((size_t)bh * 16 + kt) * S + qt * 128 + tq + i] = rmax[i];
    }
}

// ---------------- row max reduce: 16 partials -> 1 per (bh,q) ----------------
__global__ void rowmax_kernel() {
    const int idx = blockIdx.x * 256 + threadIdx.x;   // 0..65535
    const int bh = idx >> 11, q = idx & 2047;
    float m = -INFINITY;
    #pragma unroll
    for (int kt = 0; kt < 16; ++kt)
        m = fmaxf(m, g_part[((size_t)bh * 16 + kt) * S + q]);
    g_rowmax[idx] = m;
}

// ---------------- fused softmax + PV (+ normalized-attn write) ----------------
// grid (qt=32, bh=32), 256 threads. Block owns 64 q rows, full d=32, loops k.
__global__ __launch_bounds__(256, 2) void pv_kernel(
        float* __restrict__ sc, const float* __restrict__ V,
        float* __restrict__ ctx, int writeAttn) {
    const int qt = blockIdx.x, bh = blockIdx.y;
    const int b = bh >> 2, h = bh & 3;
    __shared__ float as_t[64][68];                // [k][q], pad 68: 16B-aligned rows
    __shared__ float vs[64][32];                  // [k][d]
    __shared__ float csum[64][32];                // ctx accumulator
    __shared__ float part[64][4];
    __shared__ float invs[64];
    __shared__ float mrow_s[64];
    const int tid = threadIdx.x;

    for (int i = tid; i < 64 * 32; i += 256) ((float*)csum)[i] = 0.f;
    if (tid < 64) mrow_s[tid] = g_rowmax[bh * S + qt * 64 + tid];
    __syncthreads();

    // phase 1: row sums of exp(x - m), streaming full rows once
    {
        const int row = tid >> 2, t4 = tid & 3;
        const float4* p = (const float4*)(sc + ((size_t)bh * S + qt * 64 + row) * S);
        const float m = mrow_s[row];
        float ssum = 0.f;
        for (int it = 0; it < 128; ++it) {
            float4 x = p[t4 + it * 4];
            ssum += __expf(x.x - m) + __expf(x.y - m) + __expf(x.z - m) + __expf(x.w - m);
        }
        part[row][t4] = ssum;
    }
    __syncthreads();
    if (tid < 64) invs[tid] = 1.0f / (part[tid][0] + part[tid][1] + part[tid][2] + part[tid][3]);
    __syncthreads();

    // phase 2: per 64-k tile: normalize (write attn in place), PV from smem
    float acc[8][4] = {};
    const int ksub = tid >> 6;                    // 0..3 : k-quarter
    const int rem = tid & 63;
    const int dg = (rem & 7) * 4;                 // 0..28
    const int qg = (rem >> 3) * 8;                // 0..56
    for (int kt = 0; kt < 32; ++kt) {
        for (int f = tid; f < 1024; f += 256) {   // 64 rows * 16 float4
            const int row = f >> 4, sg = (f & 15) * 4;
            const size_t gidx = (((size_t)bh * S + qt * 64 + row) * S + (size_t)kt * 64 + sg) >> 2;
            float4 x = ((const float4*)sc)[gidx];
            const float m = mrow_s[row], iv = invs[row];
            float4 e;
            e.x = __expf(x.x - m) * iv;
            e.y = __expf(x.y - m) * iv;
            e.z = __expf(x.z - m) * iv;
            e.w = __expf(x.w - m) * iv;
            if (writeAttn) ((float4*)sc)[gidx] = e;
            as_t[sg + 0][row] = e.x;
            as_t[sg + 1][row] = e.y;
            as_t[sg + 2][row] = e.z;
            as_t[sg + 3][row] = e.w;
        }
        const float4* vb = (const float4*)(V + ((size_t)bh * S + (size_t)kt * 64) * DK);
        for (int f = tid; f < 512; f += 256)
            ((float4*)vs)[f] = vb[f];
        __syncthreads();

        for (int kk = ksub * 16; kk < ksub * 16 + 16; ++kk) {
            const float4 v = *(const float4*)&vs[kk][dg];
            const float4 a0 = *(const float4*)&as_t[kk][qg];
            const float4 a1 = *(const float4*)&as_t[kk][qg + 4];
            const float aq[8] = {a0.x, a0.y, a0.z, a0.w, a1.x, a1.y, a1.z, a1.w};
            #pragma unroll
            for (int qi = 0; qi < 8; ++qi) {
                acc[qi][0] = fmaf(aq[qi], v.x, acc[qi][0]);
                acc[qi][1] = fmaf(aq[qi], v.y, acc[qi][1]);
                acc[qi][2] = fmaf(aq[qi], v.z, acc[qi][2]);
                acc[qi][3] = fmaf(aq[qi], v.w, acc[qi][3]);
            }
        }
        __syncthreads();
    }
    // combine the 4 k-quarters
    #pragma unroll
    for (int qi = 0; qi < 8; ++qi)
        #pragma unroll
        for (int di = 0; di < 4; ++di)
            atomicAdd(&csum[qg + qi][dg + di], acc[qi][di]);
    __syncthreads();
    for (int i = tid; i < 64 * 32; i += 256) {
        const int row = i >> 5, d = i & 31;
        ctx[((size_t)b * S + qt * 64 + row) * D + h * DK + d] = csum[row][d];
    }
}

// ---------------- final: y = ctx @ Wo + resid; out = layernorm(y) ----------------
__global__ __launch_bounds__(128) void out_kernel(const float* __restrict__ Wo,
                                                  float* __restrict__ out) {
    __shared__ float xs[16][128];
    __shared__ float ys[16][129];                 // padded
    __shared__ float mu[16], rstd[16];
    const int rowBase = blockIdx.x * 16;
    const int c = threadIdx.x;

    #pragma unroll
    for (int r = 0; r < 16; ++r)
        xs[r][c] = g_ctx[(size_t)(rowBase + r) * D + c];
    __syncthreads();

    float acc[16];
    #pragma unroll
    for (int r = 0; r < 16; ++r)
        acc[r] = g_resid[(size_t)(rowBase + r) * D + c];
    for (int k = 0; k < D; ++k) {
        float w = Wo[k * D + c];
        #pragma unroll
        for (int r = 0; r < 16; ++r)
            acc[r] = fmaf(xs[r][k], w, acc[r]);
    }
    #pragma unroll
    for (int r = 0; r < 16; ++r) ys[r][c] = acc[r];
    __syncthreads();

    if (c < 16) {
        float s1 = 0.f, s2 = 0.f;
        for (int k = 0; k < D; ++k) { float v = ys[c][k]; s1 += v; s2 += v * v; }
        const float m = s1 * (1.0f / D);
        const float var = s2 * (1.0f / D) - m * m;
        mu[c] = m; rstd[c] = rsqrtf(var + EPS);
    }
    __syncthreads();
    #pragma unroll
    for (int r = 0; r < 16; ++r)
        out[(size_t)(rowBase + r) * D + c] = (ys[r][c] - mu[r]) * rstd[r];
}

// ---------------- launch ----------------
extern "C" void kernel_launch(void* const* d_in, const int* in_sizes, int n_in,
                              void* d_out, int out_size) {
    const float* inQ = (const float*)d_in[0];
    const float* inK = (const float*)d_in[1];
    const float* inV = (const float*)d_in[2];
    const int*   mask = (const int*)d_in[3];      // bool stored as 4-byte (proven R7)
    const float* W0 = (const float*)d_in[4];
    const float* Wq = (const float*)d_in[5];
    const float* Wk = (const float*)d_in[6];
    const float* Wv = (const float*)d_in[7];
    const float* Wo = (const float*)d_in[8];
    float* out = (float*)d_out;

    float *resid_p, *Q_p, *K_p, *V_p, *ctx_p, *sc_p;
    cudaGetSymbolAddress((void**)&resid_p, g_resid);
    cudaGetSymbolAddress((void**)&Q_p, g_Q);
    cudaGetSymbolAddress((void**)&K_p, g_K);
    cudaGetSymbolAddress((void**)&V_p, g_V);
    cudaGetSymbolAddress((void**)&ctx_p, g_ctx);
    cudaGetSymbolAddress((void**)&sc_p, g_scores);

    const size_t normElems = (size_t)RT * D;                 // 2,097,152
    const size_t attnElems = (size_t)B * H * S * S;          // 134,217,728
    const int attnInOut = ((size_t)out_size >= normElems + attnElems);
    float* sc = attnInOut ? out + normElems : sc_p;

    // 1) projections
    proj_kernel<<<RT / 8, 128>>>(inQ, W0, resid_p, 0);
    proj_kernel<<<RT / 8, 128>>>(inQ, Wq, Q_p, 1);
    proj_kernel<<<RT / 8, 128>>>(inK, Wk, K_p, 1);
    proj_kernel<<<RT / 8, 128>>>(inV, Wv, V_p, 1);

    // 2) masked scaled scores + per-tile row maxima
    scores_kernel<<<dim3(16, 16, 32), 256>>>(Q_p, K_p, mask, sc);

    // 3) row max
    rowmax_kernel<<<256, 256>>>();

    // 4) fused softmax + PV (+ attn write when required)
    pv_kernel<<<dim3(32, 32), 256>>>(sc, V_p, ctx_p, attnInOut);

    // 5) output proj + residual + layernorm
    out_kernel<<<RT / 16, 128>>>(Wo, out);
}

// round 9
// speedup vs baseline: 1.0871x; 1.0466x over previous
#include <cuda_runtime.h>
#include <math.h>

#define B 8
#define S 2048
#define D 128
#define H 4
#define DK 32
#define RT (B*S)          // 16384 rows
#define EPS 1e-5f

// ---------------- scratch (static __device__ globals; no allocation) ----------------
__device__ float g_resid[RT * D];                 // [B*S, D]
__device__ float g_Q[RT * D];                     // [B,H,S,DK]
__device__ float g_K[RT * D];                     // [B,H,S,DK]
__device__ float g_V[RT * D];                     // [B,H,S,DK]
__device__ float g_ctx[RT * D];                   // [B,S,H*DK]
__device__ float g_part[32 * 16 * S];             // per-(bh,ktile128,q) tile max
__device__ float g_psum[32 * 16 * S];             // per-(bh,ktile128,q) sum exp(x - tilemax)
__device__ float g_rowmax[32 * S];                // per-(bh,q) row max
__device__ float g_rowinv[32 * S];                // per-(bh,q) 1/rowsum
__device__ float g_scores[134217728];             // [B,H,S,S] fallback if attn not in d_out

// ---------------- all 4 projections in one launch: blockIdx.y selects ----------------
// 128 threads, 8 rows per block. Thread c owns output column c for 8 rows.
__global__ __launch_bounds__(128) void proj_all_kernel(
        const float* __restrict__ inQ, const float* __restrict__ inK,
        const float* __restrict__ inV,
        const float* __restrict__ W0, const float* __restrict__ Wq,
        const float* __restrict__ Wk, const float* __restrict__ Wv,
        float* __restrict__ resid, float* __restrict__ Qo,
        float* __restrict__ Ko, float* __restrict__ Vo) {
    const float* X; const float* W; float* out; int headSplit;
    switch (blockIdx.y) {
        case 0: X = inQ; W = W0; out = resid; headSplit = 0; break;
        case 1: X = inQ; W = Wq; out = Qo;    headSplit = 1; break;
        case 2: X = inK; W = Wk; out = Ko;    headSplit = 1; break;
        default:X = inV; W = Wv; out = Vo;    headSplit = 1; break;
    }
    __shared__ float xs[8][128];
    const int rowBase = blockIdx.x * 8;
    const int c = threadIdx.x;                    // 0..127
    #pragma unroll
    for (int r = 0; r < 8; ++r)
        xs[r][c] = X[(size_t)(rowBase + r) * D + c];
    __syncthreads();

    float acc[8];
    #pragma unroll
    for (int r = 0; r < 8; ++r) acc[r] = 0.f;

    for (int k = 0; k < D; ++k) {
        float w = W[k * D + c];                   // coalesced; W stays L2-resident
        #pragma unroll
        for (int r = 0; r < 8; ++r)
            acc[r] = fmaf(xs[r][k], w, acc[r]);   // xs[r][k]: warp-broadcast
    }

    if (!headSplit) {
        #pragma unroll
        for (int r = 0; r < 8; ++r)
            out[(size_t)(rowBase + r) * D + c] = acc[r];
    } else {
        const int h = c >> 5, d = c & 31;
        #pragma unroll
        for (int r = 0; r < 8; ++r) {
            const int row = rowBase + r;
            const int b = row / S, s = row % S;
            out[(((size_t)(b * H + h)) * S + s) * DK + d] = acc[r];
        }
    }
}

// ---------------- scores = Q K^T / sqrt(dk), masked; emits tile max + exp-sums --------
// grid (kt=16, qt=16, bh=32), 256 threads; 128x128 tile, 8x8 micro-tile.
__global__ __launch_bounds__(256, 2) void scores_kernel(
        const float* __restrict__ Q, const float* __restrict__ K,
        const int* __restrict__ mask, float* __restrict__ sc) {
    const int kt = blockIdx.x, qt = blockIdx.y, bh = blockIdx.z;
    const int b = bh >> 2;                        // bh = b*H + h
    __shared__ float qs[128][33];
    __shared__ float ks[128][33];
    const int tid = threadIdx.x;

    const float4* Qb = (const float4*)(Q + ((size_t)bh * S + (size_t)qt * 128) * DK);
    const float4* Kb = (const float4*)(K + ((size_t)bh * S + (size_t)kt * 128) * DK);
    for (int f = tid; f < 1024; f += 256) {       // 128 rows * 8 float4
        const int row = f >> 3, sg = (f & 7) * 4;
        float4 v = Qb[f];
        qs[row][sg] = v.x; qs[row][sg+1] = v.y; qs[row][sg+2] = v.z; qs[row][sg+3] = v.w;
        v = Kb[f];
        ks[row][sg] = v.x; ks[row][sg+1] = v.y; ks[row][sg+2] = v.z; ks[row][sg+3] = v.w;
    }
    __syncthreads();

    const int tk = (tid & 15) * 8;                // 0..120
    const int tq = (tid >> 4) * 8;                // 0..120
    float acc[8][8] = {};
    for (int d = 0; d < DK; ++d) {
        float qv[8], kv[8];
        #pragma unroll
        for (int i = 0; i < 8; ++i) { qv[i] = qs[tq + i][d]; kv[i] = ks[tk + i][d]; }
        #pragma unroll
        for (int i = 0; i < 8; ++i)
            #pragma unroll
            for (int j = 0; j < 8; ++j)
                acc[i][j] = fmaf(qv[i], kv[j], acc[i][j]);
    }

    const float scale = 0.17677669529663687f;     // 1/sqrt(32)
    float rmax[8];
    #pragma unroll
    for (int i = 0; i < 8; ++i) {
        const int q = qt * 128 + tq + i;
        const int4* mrow = (const int4*)(mask + ((size_t)b * S + q) * S + (size_t)kt * 128 + tk);
        float4* srow = (float4*)(sc + ((size_t)bh * S + q) * S + (size_t)kt * 128 + tk);
        const int4 m0 = mrow[0], m1 = mrow[1];
        float4 o0, o1;
        o0.x = m0.x ? -1e9f : acc[i][0] * scale;
        o0.y = m0.y ? -1e9f : acc[i][1] * scale;
        o0.z = m0.z ? -1e9f : acc[i][2] * scale;
        o0.w = m0.w ? -1e9f : acc[i][3] * scale;
        o1.x = m1.x ? -1e9f : acc[i][4] * scale;
        o1.y = m1.y ? -1e9f : acc[i][5] * scale;
        o1.z = m1.z ? -1e9f : acc[i][6] * scale;
        o1.w = m1.w ? -1e9f : acc[i][7] * scale;
        srow[0] = o0; srow[1] = o1;
        // keep masked values for the exp pass
        acc[i][0] = o0.x; acc[i][1] = o0.y; acc[i][2] = o0.z; acc[i][3] = o0.w;
        acc[i][4] = o1.x; acc[i][5] = o1.y; acc[i][6] = o1.z; acc[i][7] = o1.w;
        rmax[i] = fmaxf(fmaxf(fmaxf(o0.x, o0.y), fmaxf(o0.z, o0.w)),
                        fmaxf(fmaxf(o1.x, o1.y), fmaxf(o1.z, o1.w)));
    }
    // reduce max across the 16 threads sharing tq (xor 1,2,4,8 stays in 16-lane halves)
    #pragma unroll
    for (int off = 1; off < 16; off <<= 1)
        #pragma unroll
        for (int i = 0; i < 8; ++i)
            rmax[i] = fmaxf(rmax[i], __shfl_xor_sync(0xffffffffu, rmax[i], off));
    // per-row sum of exp(x - tilemax), same reduction pattern
    float esum[8];
    #pragma unroll
    for (int i = 0; i < 8; ++i) {
        float s = 0.f;
        #pragma unroll
        for (int j = 0; j < 8; ++j) s += __expf(acc[i][j] - rmax[i]);
        esum[i] = s;
    }
    #pragma unroll
    for (int off = 1; off < 16; off <<= 1)
        #pragma unroll
        for (int i = 0; i < 8; ++i)
            esum[i] += __shfl_xor_sync(0xffffffffu, esum[i], off);
    if ((tid & 15) == 0) {
        #pragma unroll
        for (int i = 0; i < 8; ++i) {
            const size_t idx = ((size_t)bh * 16 + kt) * S + qt * 128 + tq + i;
            g_part[idx] = rmax[i];
            g_psum[idx] = esum[i];
        }
    }
}

// ---------------- row stats: combine 16 tile partials -> rowmax + 1/rowsum ----------
__global__ void rowstat_kernel() {
    const int idx = blockIdx.x * 256 + threadIdx.x;   // 0..65535
    const int bh = idx >> 11, q = idx & 2047;
    float m = -INFINITY;
    #pragma unroll
    for (int kt = 0; kt < 16; ++kt)
        m = fmaxf(m, g_part[((size_t)bh * 16 + kt) * S + q]);
    float s = 0.f;
    #pragma unroll
    for (int kt = 0; kt < 16; ++kt) {
        const size_t i = ((size_t)bh * 16 + kt) * S + q;
        s += g_psum[i] * __expf(g_part[i] - m);
    }
    g_rowmax[idx] = m;
    g_rowinv[idx] = 1.0f / s;
}

// ---------------- fused softmax + PV (+ normalized-attn write) ----------------
// grid (qt=32, bh=32), 256 threads. Block owns 64 q rows, full d=32, loops k.
__global__ __launch_bounds__(256, 2) void pv_kernel(
        float* __restrict__ sc, const float* __restrict__ V,
        float* __restrict__ ctx, int writeAttn) {
    const int qt = blockIdx.x, bh = blockIdx.y;
    const int b = bh >> 2, h = bh & 3;
    __shared__ float as_t[64][68];                // [k][q], pad 68: 16B-aligned rows
    __shared__ float vs[64][32];                  // [k][d]
    __shared__ float csum[64][32];                // ctx accumulator
    __shared__ float invs[64];
    __shared__ float mrow_s[64];
    const int tid = threadIdx.x;

    for (int i = tid; i < 64 * 32; i += 256) ((float*)csum)[i] = 0.f;
    if (tid < 64) {
        mrow_s[tid] = g_rowmax[bh * S + qt * 64 + tid];
        invs[tid]   = g_rowinv[bh * S + qt * 64 + tid];
    }
    __syncthreads();

    float acc[8][4] = {};
    const int ksub = tid >> 6;                    // 0..3 : k-quarter
    const int rem = tid & 63;
    const int dg = (rem & 7) * 4;                 // 0..28
    const int qg = (rem >> 3) * 8;                // 0..56
    for (int kt = 0; kt < 32; ++kt) {
        for (int f = tid; f < 1024; f += 256) {   // 64 rows * 16 float4
            const int row = f >> 4, sg = (f & 15) * 4;
            const size_t gidx = (((size_t)bh * S + qt * 64 + row) * S + (size_t)kt * 64 + sg) >> 2;
            float4 x = ((const float4*)sc)[gidx];
            const float m = mrow_s[row], iv = invs[row];
            float4 e;
            e.x = __expf(x.x - m) * iv;
            e.y = __expf(x.y - m) * iv;
            e.z = __expf(x.z - m) * iv;
            e.w = __expf(x.w - m) * iv;
            if (writeAttn) ((float4*)sc)[gidx] = e;
            as_t[sg + 0][row] = e.x;
            as_t[sg + 1][row] = e.y;
            as_t[sg + 2][row] = e.z;
            as_t[sg + 3][row] = e.w;
        }
        const float4* vb = (const float4*)(V + ((size_t)bh * S + (size_t)kt * 64) * DK);
        for (int f = tid; f < 512; f += 256)
            ((float4*)vs)[f] = vb[f];
        __syncthreads();

        for (int kk = ksub * 16; kk < ksub * 16 + 16; ++kk) {
            const float4 v = *(const float4*)&vs[kk][dg];
            const float4 a0 = *(const float4*)&as_t[kk][qg];
            const float4 a1 = *(const float4*)&as_t[kk][qg + 4];
            const float aq[8] = {a0.x, a0.y, a0.z, a0.w, a1.x, a1.y, a1.z, a1.w};
            #pragma unroll
            for (int qi = 0; qi < 8; ++qi) {
                acc[qi][0] = fmaf(aq[qi], v.x, acc[qi][0]);
                acc[qi][1] = fmaf(aq[qi], v.y, acc[qi][1]);
                acc[qi][2] = fmaf(aq[qi], v.z, acc[qi][2]);
                acc[qi][3] = fmaf(aq[qi], v.w, acc[qi][3]);
            }
        }
        __syncthreads();
    }
    // combine the 4 k-quarters
    #pragma unroll
    for (int qi = 0; qi < 8; ++qi)
        #pragma unroll
        for (int di = 0; di < 4; ++di)
            atomicAdd(&csum[qg + qi][dg + di], acc[qi][di]);
    __syncthreads();
    for (int i = tid; i < 64 * 32; i += 256) {
        const int row = i >> 5, d = i & 31;
        ctx[((size_t)b * S + qt * 64 + row) * D + h * DK + d] = csum[row][d];
    }
}

// ---------------- final: y = ctx @ Wo + resid; out = layernorm(y) ----------------
__global__ __launch_bounds__(128) void out_kernel(const float* __restrict__ Wo,
                                                  float* __restrict__ out) {
    __shared__ float xs[16][128];
    __shared__ float ys[16][129];                 // padded
    __shared__ float mu[16], rstd[16];
    const int rowBase = blockIdx.x * 16;
    const int c = threadIdx.x;

    #pragma unroll
    for (int r = 0; r < 16; ++r)
        xs[r][c] = g_ctx[(size_t)(rowBase + r) * D + c];
    __syncthreads();

    float acc[16];
    #pragma unroll
    for (int r = 0; r < 16; ++r)
        acc[r] = g_resid[(size_t)(rowBase + r) * D + c];
    for (int k = 0; k < D; ++k) {
        float w = Wo[k * D + c];
        #pragma unroll
        for (int r = 0; r < 16; ++r)
            acc[r] = fmaf(xs[r][k], w, acc[r]);
    }
    #pragma unroll
    for (int r = 0; r < 16; ++r) ys[r][c] = acc[r];
    __syncthreads();

    if (c < 16) {
        float s1 = 0.f, s2 = 0.f;
        for (int k = 0; k < D; ++k) { float v = ys[c][k]; s1 += v; s2 += v * v; }
        const float m = s1 * (1.0f / D);
        const float var = s2 * (1.0f / D) - m * m;
        mu[c] = m; rstd[c] = rsqrtf(var + EPS);
    }
    __syncthreads();
    #pragma unroll
    for (int r = 0; r < 16; ++r)
        out[(size_t)(rowBase + r) * D + c] = (ys[r][c] - mu[r]) * rstd[r];
}

// ---------------- launch ----------------
extern "C" void kernel_launch(void* const* d_in, const int* in_sizes, int n_in,
                              void* d_out, int out_size) {
    const float* inQ = (const float*)d_in[0];
    const float* inK = (const float*)d_in[1];
    const float* inV = (const float*)d_in[2];
    const int*   mask = (const int*)d_in[3];      // bool stored as 4-byte (proven R7)
    const float* W0 = (const float*)d_in[4];
    const float* Wq = (const float*)d_in[5];
    const float* Wk = (const float*)d_in[6];
    const float* Wv = (const float*)d_in[7];
    const float* Wo = (const float*)d_in[8];
    float* out = (float*)d_out;

    float *resid_p, *Q_p, *K_p, *V_p, *ctx_p, *sc_p;
    cudaGetSymbolAddress((void**)&resid_p, g_resid);
    cudaGetSymbolAddress((void**)&Q_p, g_Q);
    cudaGetSymbolAddress((void**)&K_p, g_K);
    cudaGetSymbolAddress((void**)&V_p, g_V);
    cudaGetSymbolAddress((void**)&ctx_p, g_ctx);
    cudaGetSymbolAddress((void**)&sc_p, g_scores);

    const size_t normElems = (size_t)RT * D;                 // 2,097,152
    const size_t attnElems = (size_t)B * H * S * S;          // 134,217,728
    const int attnInOut = ((size_t)out_size >= normElems + attnElems);
    float* sc = attnInOut ? out + normElems : sc_p;

    // 1) all projections, one launch
    proj_all_kernel<<<dim3(RT / 8, 4), 128>>>(inQ, inK, inV, W0, Wq, Wk, Wv,
                                              resid_p, Q_p, K_p, V_p);

    // 2) masked scaled scores + per-tile (max, exp-sum) partials
    scores_kernel<<<dim3(16, 16, 32), 256>>>(Q_p, K_p, mask, sc);

    // 3) row stats (max + inverse sum) -- no pass over the scores tensor
    rowstat_kernel<<<256, 256>>>();

    // 4) fused softmax + PV (+ attn write when required)
    pv_kernel<<<dim3(32, 32), 256>>>(sc, V_p, ctx_p, attnInOut);

    // 5) output proj + residual + layernorm
    out_kernel<<<RT / 16, 128>>>(Wo, out);
}

// round 10
// speedup vs baseline: 1.2853x; 1.1824x over previous
#include <cuda_runtime.h>
#include <math.h>

#define B 8
#define S 2048
#define D 128
#define H 4
#define DK 32
#define RT (B*S)          // 16384 rows
#define EPS 1e-5f

// ---------------- scratch (static __device__ globals; no allocation) ----------------
__device__ float g_resid[RT * D];                 // [B*S, D]
__device__ float g_Q[RT * D];                     // [B,H,S,DK]
__device__ float g_K[RT * D];                     // [B,H,S,DK]
__device__ float g_V[RT * D];                     // [B,H,S,DK]
__device__ float g_ctx[RT * D];                   // [B,S,H*DK]
__device__ float g_part[32 * 16 * S];             // per-(bh,ktile128,q) tile max
__device__ float g_psum[32 * 16 * S];             // per-(bh,ktile128,q) sum exp(x - tilemax)
__device__ float g_rowmax[32 * S];                // per-(bh,q) row max
__device__ float g_rowinv[32 * S];                // per-(bh,q) 1/rowsum
__device__ float g_scores[134217728];             // [B,H,S,S] fallback if attn not in d_out

// ---------------- zero ctx (atomic accumulation target) ----------------
__global__ void zero_ctx_kernel(float* __restrict__ ctx) {
    const int i = blockIdx.x * 256 + threadIdx.x;
    ((float4*)ctx)[i] = make_float4(0.f, 0.f, 0.f, 0.f);
}

// ---------------- all 4 projections in one launch: blockIdx.y selects ----------------
__global__ __launch_bounds__(128) void proj_all_kernel(
        const float* __restrict__ inQ, const float* __restrict__ inK,
        const float* __restrict__ inV,
        const float* __restrict__ W0, const float* __restrict__ Wq,
        const float* __restrict__ Wk, const float* __restrict__ Wv,
        float* __restrict__ resid, float* __restrict__ Qo,
        float* __restrict__ Ko, float* __restrict__ Vo) {
    const float* X; const float* W; float* out; int headSplit;
    switch (blockIdx.y) {
        case 0: X = inQ; W = W0; out = resid; headSplit = 0; break;
        case 1: X = inQ; W = Wq; out = Qo;    headSplit = 1; break;
        case 2: X = inK; W = Wk; out = Ko;    headSplit = 1; break;
        default:X = inV; W = Wv; out = Vo;    headSplit = 1; break;
    }
    __shared__ float xs[8][128];
    const int rowBase = blockIdx.x * 8;
    const int c = threadIdx.x;                    // 0..127
    #pragma unroll
    for (int r = 0; r < 8; ++r)
        xs[r][c] = X[(size_t)(rowBase + r) * D + c];
    __syncthreads();

    float acc[8];
    #pragma unroll
    for (int r = 0; r < 8; ++r) acc[r] = 0.f;

    for (int k = 0; k < D; ++k) {
        float w = W[k * D + c];
        #pragma unroll
        for (int r = 0; r < 8; ++r)
            acc[r] = fmaf(xs[r][k], w, acc[r]);
    }

    if (!headSplit) {
        #pragma unroll
        for (int r = 0; r < 8; ++r)
            out[(size_t)(rowBase + r) * D + c] = acc[r];
    } else {
        const int h = c >> 5, d = c & 31;
        #pragma unroll
        for (int r = 0; r < 8; ++r) {
            const int row = rowBase + r;
            const int b = row / S, s = row % S;
            out[(((size_t)(b * H + h)) * S + s) * DK + d] = acc[r];
        }
    }
}

// ---------------- scores tile: writes e = exp(x - tilemax); emits (tilemax, expsum) ---
// grid (kt=16, qt=16, bh=32), 256 threads; 128x128 tile, 8x8 micro-tile.
__global__ __launch_bounds__(256, 2) void scores_kernel(
        const float* __restrict__ Q, const float* __restrict__ K,
        const int* __restrict__ mask, float* __restrict__ sc) {
    const int kt = blockIdx.x, qt = blockIdx.y, bh = blockIdx.z;
    const int b = bh >> 2;                        // bh = b*H + h
    __shared__ float qs[128][33];
    __shared__ float ks[128][33];
    const int tid = threadIdx.x;

    const float4* Qb = (const float4*)(Q + ((size_t)bh * S + (size_t)qt * 128) * DK);
    const float4* Kb = (const float4*)(K + ((size_t)bh * S + (size_t)kt * 128) * DK);
    for (int f = tid; f < 1024; f += 256) {       // 128 rows * 8 float4
        const int row = f >> 3, sg = (f & 7) * 4;
        float4 v = Qb[f];
        qs[row][sg] = v.x; qs[row][sg+1] = v.y; qs[row][sg+2] = v.z; qs[row][sg+3] = v.w;
        v = Kb[f];
        ks[row][sg] = v.x; ks[row][sg+1] = v.y; ks[row][sg+2] = v.z; ks[row][sg+3] = v.w;
    }
    __syncthreads();

    const int tk = (tid & 15) * 8;                // 0..120
    const int tq = (tid >> 4) * 8;                // 0..120
    float acc[8][8] = {};
    for (int d = 0; d < DK; ++d) {
        float qv[8], kv[8];
        #pragma unroll
        for (int i = 0; i < 8; ++i) { qv[i] = qs[tq + i][d]; kv[i] = ks[tk + i][d]; }
        #pragma unroll
        for (int i = 0; i < 8; ++i)
            #pragma unroll
            for (int j = 0; j < 8; ++j)
                acc[i][j] = fmaf(qv[i], kv[j], acc[i][j]);
    }

    const float scale = 0.17677669529663687f;     // 1/sqrt(32)
    float rmax[8];
    #pragma unroll
    for (int i = 0; i < 8; ++i) {
        const int q = qt * 128 + tq + i;
        const int4* mrow = (const int4*)(mask + ((size_t)b * S + q) * S + (size_t)kt * 128 + tk);
        const int4 m0 = mrow[0], m1 = mrow[1];
        acc[i][0] = m0.x ? -1e9f : acc[i][0] * scale;
        acc[i][1] = m0.y ? -1e9f : acc[i][1] * scale;
        acc[i][2] = m0.z ? -1e9f : acc[i][2] * scale;
        acc[i][3] = m0.w ? -1e9f : acc[i][3] * scale;
        acc[i][4] = m1.x ? -1e9f : acc[i][4] * scale;
        acc[i][5] = m1.y ? -1e9f : acc[i][5] * scale;
        acc[i][6] = m1.z ? -1e9f : acc[i][6] * scale;
        acc[i][7] = m1.w ? -1e9f : acc[i][7] * scale;
        float mx = fmaxf(fmaxf(fmaxf(acc[i][0], acc[i][1]), fmaxf(acc[i][2], acc[i][3])),
                         fmaxf(fmaxf(acc[i][4], acc[i][5]), fmaxf(acc[i][6], acc[i][7])));
        rmax[i] = mx;
    }
    // reduce max across the 16 threads sharing tq (xor 1..8 stays in 16-lane halves)
    #pragma unroll
    for (int off = 1; off < 16; off <<= 1)
        #pragma unroll
        for (int i = 0; i < 8; ++i)
            rmax[i] = fmaxf(rmax[i], __shfl_xor_sync(0xffffffffu, rmax[i], off));
    // e = exp(x - tilemax): store it (this IS what pv consumes) + per-row sums
    float esum[8];
    #pragma unroll
    for (int i = 0; i < 8; ++i) {
        float4 e0, e1;
        e0.x = __expf(acc[i][0] - rmax[i]);
        e0.y = __expf(acc[i][1] - rmax[i]);
        e0.z = __expf(acc[i][2] - rmax[i]);
        e0.w = __expf(acc[i][3] - rmax[i]);
        e1.x = __expf(acc[i][4] - rmax[i]);
        e1.y = __expf(acc[i][5] - rmax[i]);
        e1.z = __expf(acc[i][6] - rmax[i]);
        e1.w = __expf(acc[i][7] - rmax[i]);
        esum[i] = (e0.x + e0.y + e0.z + e0.w) + (e1.x + e1.y + e1.z + e1.w);
        float4* srow = (float4*)(sc + ((size_t)bh * S + qt * 128 + tq + i) * S + (size_t)kt * 128 + tk);
        srow[0] = e0; srow[1] = e1;
    }
    #pragma unroll
    for (int off = 1; off < 16; off <<= 1)
        #pragma unroll
        for (int i = 0; i < 8; ++i)
            esum[i] += __shfl_xor_sync(0xffffffffu, esum[i], off);
    if ((tid & 15) == 0) {
        #pragma unroll
        for (int i = 0; i < 8; ++i) {
            const size_t idx = ((size_t)bh * 16 + kt) * S + qt * 128 + tq + i;
            g_part[idx] = rmax[i];
            g_psum[idx] = esum[i];
        }
    }
}

// ---------------- row stats: combine 16 tile partials -> rowmax + 1/rowsum ----------
__global__ void rowstat_kernel() {
    const int idx = blockIdx.x * 256 + threadIdx.x;   // 0..65535
    const int bh = idx >> 11, q = idx & 2047;
    float m = -INFINITY;
    #pragma unroll
    for (int kt = 0; kt < 16; ++kt)
        m = fmaxf(m, g_part[((size_t)bh * 16 + kt) * S + q]);
    float s = 0.f;
    #pragma unroll
    for (int kt = 0; kt < 16; ++kt) {
        const size_t i = ((size_t)bh * 16 + kt) * S + q;
        s += g_psum[i] * __expf(g_part[i] - m);
    }
    g_rowmax[idx] = m;
    g_rowinv[idx] = 1.0f / s;
}

// ---------------- k-partitioned attn-normalize + partial PV ----------------
// grid (kt=32, qt=32, bh=32); block: one 64q x 64k tile; accumulates ctx via atomics.
__global__ __launch_bounds__(256, 4) void pv_kernel(
        float* __restrict__ sc, const float* __restrict__ V,
        float* __restrict__ ctx, int writeAttn) {
    const int kt = blockIdx.x, qt = blockIdx.y, bh = blockIdx.z;
    const int b = bh >> 2, h = bh & 3;
    __shared__ float as_t[64][68];                // attn transposed [k][q]; 16B-aligned rows
    __shared__ float vs[64][32];                  // [k][d]
    __shared__ float fac[64];                     // exp(tilemax - rowmax) / rowsum
    const int tid = threadIdx.x;

    if (tid < 64) {
        const int q = qt * 64 + tid;
        const float mt = g_part[((size_t)bh * 16 + (kt >> 1)) * S + q];
        fac[tid] = __expf(mt - g_rowmax[bh * S + q]) * g_rowinv[bh * S + q];
    }
    __syncthreads();

    // load e tile, scale to final attn, write back, transpose into smem
    for (int f = tid; f < 1024; f += 256) {       // 64 rows * 16 float4
        const int row = f >> 4, sg = (f & 15) * 4;
        const size_t gidx = (((size_t)bh * S + qt * 64 + row) * S + (size_t)kt * 64 + sg) >> 2;
        float4 x = ((const float4*)sc)[gidx];
        const float fv = fac[row];
        x.x *= fv; x.y *= fv; x.z *= fv; x.w *= fv;
        if (writeAttn) ((float4*)sc)[gidx] = x;
        as_t[sg + 0][row] = x.x;
        as_t[sg + 1][row] = x.y;
        as_t[sg + 2][row] = x.z;
        as_t[sg + 3][row] = x.w;
    }
    const float4* vb = (const float4*)(V + ((size_t)bh * S + (size_t)kt * 64) * DK);
    for (int f = tid; f < 512; f += 256)
        ((float4*)vs)[f] = vb[f];
    __syncthreads();

    // PV: thread owns 8 q rows x 1 d column, full 64 k
    const int d  = tid & 31;
    const int qg = (tid >> 5) * 8;                // 0..56
    float acc[8] = {};
    for (int kk = 0; kk < 64; ++kk) {
        const float v = vs[kk][d];                // conflict-free across warp
        const float4 a0 = *(const float4*)&as_t[kk][qg];      // warp-broadcast
        const float4 a1 = *(const float4*)&as_t[kk][qg + 4];  // warp-broadcast
        acc[0] = fmaf(a0.x, v, acc[0]);
        acc[1] = fmaf(a0.y, v, acc[1]);
        acc[2] = fmaf(a0.z, v, acc[2]);
        acc[3] = fmaf(a0.w, v, acc[3]);
        acc[4] = fmaf(a1.x, v, acc[4]);
        acc[5] = fmaf(a1.y, v, acc[5]);
        acc[6] = fmaf(a1.z, v, acc[6]);
        acc[7] = fmaf(a1.w, v, acc[7]);
    }
    #pragma unroll
    for (int i = 0; i < 8; ++i)
        atomicAdd(&ctx[((size_t)b * S + qt * 64 + qg + i) * D + h * DK + d], acc[i]);
}

// ---------------- final: y = ctx @ Wo + resid; out = layernorm(y) ----------------
__global__ __launch_bounds__(128) void out_kernel(const float* __restrict__ Wo,
                                                  float* __restrict__ out) {
    __shared__ float xs[16][128];
    __shared__ float ys[16][129];                 // padded
    __shared__ float mu[16], rstd[16];
    const int rowBase = blockIdx.x * 16;
    const int c = threadIdx.x;

    #pragma unroll
    for (int r = 0; r < 16; ++r)
        xs[r][c] = g_ctx[(size_t)(rowBase + r) * D + c];
    __syncthreads();

    float acc[16];
    #pragma unroll
    for (int r = 0; r < 16; ++r)
        acc[r] = g_resid[(size_t)(rowBase + r) * D + c];
    for (int k = 0; k < D; ++k) {
        float w = Wo[k * D + c];
        #pragma unroll
        for (int r = 0; r < 16; ++r)
            acc[r] = fmaf(xs[r][k], w, acc[r]);
    }
    #pragma unroll
    for (int r = 0; r < 16; ++r) ys[r][c] = acc[r];
    __syncthreads();

    if (c < 16) {
        float s1 = 0.f, s2 = 0.f;
        for (int k = 0; k < D; ++k) { float v = ys[c][k]; s1 += v; s2 += v * v; }
        const float m = s1 * (1.0f / D);
        const float var = s2 * (1.0f / D) - m * m;
        mu[c] = m; rstd[c] = rsqrtf(var + EPS);
    }
    __syncthreads();
    #pragma unroll
    for (int r = 0; r < 16; ++r)
        out[(size_t)(rowBase + r) * D + c] = (ys[r][c] - mu[r]) * rstd[r];
}

// ---------------- launch ----------------
extern "C" void kernel_launch(void* const* d_in, const int* in_sizes, int n_in,
                              void* d_out, int out_size) {
    const float* inQ = (const float*)d_in[0];
    const float* inK = (const float*)d_in[1];
    const float* inV = (const float*)d_in[2];
    const int*   mask = (const int*)d_in[3];      // bool stored as 4-byte (proven R7)
    const float* W0 = (const float*)d_in[4];
    const float* Wq = (const float*)d_in[5];
    const float* Wk = (const float*)d_in[6];
    const float* Wv = (const float*)d_in[7];
    const float* Wo = (const float*)d_in[8];
    float* out = (float*)d_out;

    float *resid_p, *Q_p, *K_p, *V_p, *ctx_p, *sc_p;
    cudaGetSymbolAddress((void**)&resid_p, g_resid);
    cudaGetSymbolAddress((void**)&Q_p, g_Q);
    cudaGetSymbolAddress((void**)&K_p, g_K);
    cudaGetSymbolAddress((void**)&V_p, g_V);
    cudaGetSymbolAddress((void**)&ctx_p, g_ctx);
    cudaGetSymbolAddress((void**)&sc_p, g_scores);

    const size_t normElems = (size_t)RT * D;                 // 2,097,152
    const size_t attnElems = (size_t)B * H * S * S;          // 134,217,728
    const int attnInOut = ((size_t)out_size >= normElems + attnElems);
    float* sc = attnInOut ? out + normElems : sc_p;

    // 0) zero the atomic-accumulated ctx
    zero_ctx_kernel<<<RT * D / 4 / 256, 256>>>(ctx_p);

    // 1) all projections, one launch
    proj_all_kernel<<<dim3(RT / 8, 4), 128>>>(inQ, inK, inV, W0, Wq, Wk, Wv,
                                              resid_p, Q_p, K_p, V_p);

    // 2) e = exp(scores - tilemax) + per-tile (max, expsum) partials
    scores_kernel<<<dim3(16, 16, 32), 256>>>(Q_p, K_p, mask, sc);

    // 3) row stats (max + inverse sum)
    rowstat_kernel<<<256, 256>>>();

    // 4) k-partitioned normalize + attn write + partial PV (atomic ctx)
    pv_kernel<<<dim3(32, 32, 32), 256>>>(sc, V_p, ctx_p, attnInOut);

    // 5) output proj + residual + layernorm
    out_kernel<<<RT / 16, 128>>>(Wo, out);
}

// round 11
// speedup vs baseline: 1.2889x; 1.0028x over previous
#include <cuda_runtime.h>
#include <math.h>

#define B 8
#define S 2048
#define D 128
#define H 4
#define DK 32
#define RT (B*S)          // 16384 rows
#define EPS 1e-5f

// ---------------- scratch (static __device__ globals; no allocation) ----------------
__device__ float g_resid[RT * D];                 // [B*S, D]
__device__ float g_Q[RT * D];                     // [B,H,S,DK]
__device__ float g_K[RT * D];                     // [B,H,S,DK]
__device__ float g_V[RT * D];                     // [B,H,S,DK]
__device__ float g_ctx[RT * D];                   // [B,S,H*DK]
__device__ float g_part[32 * 16 * S];             // per-(bh,ktile128,q) tile max
__device__ float g_psum[32 * 16 * S];             // per-(bh,ktile128,q) sum exp(x - tilemax)
__device__ float g_rowmax[32 * S];                // per-(bh,q) row max
__device__ float g_rowinv[32 * S];                // per-(bh,q) 1/rowsum
__device__ float g_scores[134217728];             // [B,H,S,S] fallback if attn not in d_out

// ---------------- zero ctx (atomic accumulation target) ----------------
__global__ void zero_ctx_kernel(float* __restrict__ ctx) {
    const int i = blockIdx.x * 256 + threadIdx.x;
    ((float4*)ctx)[i] = make_float4(0.f, 0.f, 0.f, 0.f);
}

// ---------------- all 4 projections in one launch: blockIdx.y selects ----------------
__global__ __launch_bounds__(128) void proj_all_kernel(
        const float* __restrict__ inQ, const float* __restrict__ inK,
        const float* __restrict__ inV,
        const float* __restrict__ W0, const float* __restrict__ Wq,
        const float* __restrict__ Wk, const float* __restrict__ Wv,
        float* __restrict__ resid, float* __restrict__ Qo,
        float* __restrict__ Ko, float* __restrict__ Vo) {
    const float* X; const float* W; float* out; int headSplit;
    switch (blockIdx.y) {
        case 0: X = inQ; W = W0; out = resid; headSplit = 0; break;
        case 1: X = inQ; W = Wq; out = Qo;    headSplit = 1; break;
        case 2: X = inK; W = Wk; out = Ko;    headSplit = 1; break;
        default:X = inV; W = Wv; out = Vo;    headSplit = 1; break;
    }
    __shared__ float xs[8][128];
    const int rowBase = blockIdx.x * 8;
    const int c = threadIdx.x;                    // 0..127
    #pragma unroll
    for (int r = 0; r < 8; ++r)
        xs[r][c] = X[(size_t)(rowBase + r) * D + c];
    __syncthreads();

    float acc[8];
    #pragma unroll
    for (int r = 0; r < 8; ++r) acc[r] = 0.f;

    for (int k = 0; k < D; ++k) {
        float w = W[k * D + c];
        #pragma unroll
        for (int r = 0; r < 8; ++r)
            acc[r] = fmaf(xs[r][k], w, acc[r]);
    }

    if (!headSplit) {
        #pragma unroll
        for (int r = 0; r < 8; ++r)
            out[(size_t)(rowBase + r) * D + c] = acc[r];
    } else {
        const int h = c >> 5, d = c & 31;
        #pragma unroll
        for (int r = 0; r < 8; ++r) {
            const int row = rowBase + r;
            const int b = row / S, s = row % S;
            out[(((size_t)(b * H + h)) * S + s) * DK + d] = acc[r];
        }
    }
}

// ---------------- scores tile: writes e = exp(x - tilemax); emits (tilemax, expsum) ---
// grid (kt=16, qt=16, bh=32), 256 threads; 128x128 tile, 8x8 micro-tile.
__global__ __launch_bounds__(256, 2) void scores_kernel(
        const float* __restrict__ Q, const float* __restrict__ K,
        const int* __restrict__ mask, float* __restrict__ sc) {
    const int kt = blockIdx.x, qt = blockIdx.y, bh = blockIdx.z;
    const int b = bh >> 2;                        // bh = b*H + h
    __shared__ float qs[128][33];
    __shared__ float ks[128][33];
    const int tid = threadIdx.x;

    const float4* Qb = (const float4*)(Q + ((size_t)bh * S + (size_t)qt * 128) * DK);
    const float4* Kb = (const float4*)(K + ((size_t)bh * S + (size_t)kt * 128) * DK);
    for (int f = tid; f < 1024; f += 256) {       // 128 rows * 8 float4
        const int row = f >> 3, sg = (f & 7) * 4;
        float4 v = Qb[f];
        qs[row][sg] = v.x; qs[row][sg+1] = v.y; qs[row][sg+2] = v.z; qs[row][sg+3] = v.w;
        v = Kb[f];
        ks[row][sg] = v.x; ks[row][sg+1] = v.y; ks[row][sg+2] = v.z; ks[row][sg+3] = v.w;
    }
    __syncthreads();

    const int tk = (tid & 15) * 8;                // 0..120
    const int tq = (tid >> 4) * 8;                // 0..120
    float acc[8][8] = {};
    for (int d = 0; d < DK; ++d) {
        float qv[8], kv[8];
        #pragma unroll
        for (int i = 0; i < 8; ++i) { qv[i] = qs[tq + i][d]; kv[i] = ks[tk + i][d]; }
        #pragma unroll
        for (int i = 0; i < 8; ++i)
            #pragma unroll
            for (int j = 0; j < 8; ++j)
                acc[i][j] = fmaf(qv[i], kv[j], acc[i][j]);
    }

    const float scale = 0.17677669529663687f;     // 1/sqrt(32)
    float rmax[8];
    #pragma unroll
    for (int i = 0; i < 8; ++i) {
        const int q = qt * 128 + tq + i;
        const int4* mrow = (const int4*)(mask + ((size_t)b * S + q) * S + (size_t)kt * 128 + tk);
        const int4 m0 = mrow[0], m1 = mrow[1];
        acc[i][0] = m0.x ? -1e9f : acc[i][0] * scale;
        acc[i][1] = m0.y ? -1e9f : acc[i][1] * scale;
        acc[i][2] = m0.z ? -1e9f : acc[i][2] * scale;
        acc[i][3] = m0.w ? -1e9f : acc[i][3] * scale;
        acc[i][4] = m1.x ? -1e9f : acc[i][4] * scale;
        acc[i][5] = m1.y ? -1e9f : acc[i][5] * scale;
        acc[i][6] = m1.z ? -1e9f : acc[i][6] * scale;
        acc[i][7] = m1.w ? -1e9f : acc[i][7] * scale;
        float mx = fmaxf(fmaxf(fmaxf(acc[i][0], acc[i][1]), fmaxf(acc[i][2], acc[i][3])),
                         fmaxf(fmaxf(acc[i][4], acc[i][5]), fmaxf(acc[i][6], acc[i][7])));
        rmax[i] = mx;
    }
    // reduce max across the 16 threads sharing tq (xor 1..8 stays in 16-lane halves)
    #pragma unroll
    for (int off = 1; off < 16; off <<= 1)
        #pragma unroll
        for (int i = 0; i < 8; ++i)
            rmax[i] = fmaxf(rmax[i], __shfl_xor_sync(0xffffffffu, rmax[i], off));
    // e = exp(x - tilemax): store it (this IS what pv consumes) + per-row sums
    float esum[8];
    #pragma unroll
    for (int i = 0; i < 8; ++i) {
        float4 e0, e1;
        e0.x = __expf(acc[i][0] - rmax[i]);
        e0.y = __expf(acc[i][1] - rmax[i]);
        e0.z = __expf(acc[i][2] - rmax[i]);
        e0.w = __expf(acc[i][3] - rmax[i]);
        e1.x = __expf(acc[i][4] - rmax[i]);
        e1.y = __expf(acc[i][5] - rmax[i]);
        e1.z = __expf(acc[i][6] - rmax[i]);
        e1.w = __expf(acc[i][7] - rmax[i]);
        esum[i] = (e0.x + e0.y + e0.z + e0.w) + (e1.x + e1.y + e1.z + e1.w);
        float4* srow = (float4*)(sc + ((size_t)bh * S + qt * 128 + tq + i) * S + (size_t)kt * 128 + tk);
        srow[0] = e0; srow[1] = e1;
    }
    #pragma unroll
    for (int off = 1; off < 16; off <<= 1)
        #pragma unroll
        for (int i = 0; i < 8; ++i)
            esum[i] += __shfl_xor_sync(0xffffffffu, esum[i], off);
    if ((tid & 15) == 0) {
        #pragma unroll
        for (int i = 0; i < 8; ++i) {
            const size_t idx = ((size_t)bh * 16 + kt) * S + qt * 128 + tq + i;
            g_part[idx] = rmax[i];
            g_psum[idx] = esum[i];
        }
    }
}

// ---------------- row stats: combine 16 tile partials -> rowmax + 1/rowsum ----------
__global__ void rowstat_kernel() {
    const int idx = blockIdx.x * 256 + threadIdx.x;   // 0..65535
    const int bh = idx >> 11, q = idx & 2047;
    float m = -INFINITY;
    #pragma unroll
    for (int kt = 0; kt < 16; ++kt)
        m = fmaxf(m, g_part[((size_t)bh * 16 + kt) * S + q]);
    float s = 0.f;
    #pragma unroll
    for (int kt = 0; kt < 16; ++kt) {
        const size_t i = ((size_t)bh * 16 + kt) * S + q;
        s += g_psum[i] * __expf(g_part[i] - m);
    }
    g_rowmax[idx] = m;
    g_rowinv[idx] = 1.0f / s;
}

// ---------------- k-partitioned attn-normalize + partial PV ----------------
// grid (kt=32, qt=32, bh=32); block: one 64q x 64k tile; accumulates ctx via atomics.
__global__ __launch_bounds__(256, 4) void pv_kernel(
        float* __restrict__ sc, const float* __restrict__ V,
        float* __restrict__ ctx, int writeAttn) {
    const int kt = blockIdx.x, qt = blockIdx.y, bh = blockIdx.z;
    const int b = bh >> 2, h = bh & 3;
    __shared__ float as_t[64][68];                // attn transposed [k][q]; 16B-aligned rows
    __shared__ float vs[64][32];                  // [k][d]
    __shared__ float fac[64];                     // exp(tilemax - rowmax) / rowsum
    const int tid = threadIdx.x;

    if (tid < 64) {
        const int q = qt * 64 + tid;
        const float mt = g_part[((size_t)bh * 16 + (kt >> 1)) * S + q];
        fac[tid] = __expf(mt - g_rowmax[bh * S + q]) * g_rowinv[bh * S + q];
    }
    __syncthreads();

    // load e tile, scale to final attn, write back, transpose into smem
    for (int f = tid; f < 1024; f += 256) {       // 64 rows * 16 float4
        const int row = f >> 4, sg = (f & 15) * 4;
        const size_t gidx = (((size_t)bh * S + qt * 64 + row) * S + (size_t)kt * 64 + sg) >> 2;
        float4 x = ((const float4*)sc)[gidx];
        const float fv = fac[row];
        x.x *= fv; x.y *= fv; x.z *= fv; x.w *= fv;
        if (writeAttn) ((float4*)sc)[gidx] = x;
        as_t[sg + 0][row] = x.x;
        as_t[sg + 1][row] = x.y;
        as_t[sg + 2][row] = x.z;
        as_t[sg + 3][row] = x.w;
    }
    const float4* vb = (const float4*)(V + ((size_t)bh * S + (size_t)kt * 64) * DK);
    for (int f = tid; f < 512; f += 256)
        ((float4*)vs)[f] = vb[f];
    __syncthreads();

    // PV: thread owns 8 q rows x 1 d column, full 64 k
    const int d  = tid & 31;
    const int qg = (tid >> 5) * 8;                // 0..56
    float acc[8] = {};
    for (int kk = 0; kk < 64; ++kk) {
        const float v = vs[kk][d];                // conflict-free across warp
        const float4 a0 = *(const float4*)&as_t[kk][qg];      // warp-broadcast
        const float4 a1 = *(const float4*)&as_t[kk][qg + 4];  // warp-broadcast
        acc[0] = fmaf(a0.x, v, acc[0]);
        acc[1] = fmaf(a0.y, v, acc[1]);
        acc[2] = fmaf(a0.z, v, acc[2]);
        acc[3] = fmaf(a0.w, v, acc[3]);
        acc[4] = fmaf(a1.x, v, acc[4]);
        acc[5] = fmaf(a1.y, v, acc[5]);
        acc[6] = fmaf(a1.z, v, acc[6]);
        acc[7] = fmaf(a1.w, v, acc[7]);
    }
    #pragma unroll
    for (int i = 0; i < 8; ++i)
        atomicAdd(&ctx[((size_t)b * S + qt * 64 + qg + i) * D + h * DK + d], acc[i]);
}

// ---------------- final: y = ctx @ Wo + resid; out = layernorm(y) ----------------
__global__ __launch_bounds__(128) void out_kernel(const float* __restrict__ Wo,
                                                  float* __restrict__ out) {
    __shared__ float xs[16][128];
    __shared__ float ys[16][129];                 // padded
    __shared__ float mu[16], rstd[16];
    const int rowBase = blockIdx.x * 16;
    const int c = threadIdx.x;

    #pragma unroll
    for (int r = 0; r < 16; ++r)
        xs[r][c] = g_ctx[(size_t)(rowBase + r) * D + c];
    __syncthreads();

    float acc[16];
    #pragma unroll
    for (int r = 0; r < 16; ++r)
        acc[r] = g_resid[(size_t)(rowBase + r) * D + c];
    for (int k = 0; k < D; ++k) {
        float w = Wo[k * D + c];
        #pragma unroll
        for (int r = 0; r < 16; ++r)
            acc[r] = fmaf(xs[r][k], w, acc[r]);
    }
    #pragma unroll
    for (int r = 0; r < 16; ++r) ys[r][c] = acc[r];
    __syncthreads();

    if (c < 16) {
        float s1 = 0.f, s2 = 0.f;
        for (int k = 0; k < D; ++k) { float v = ys[c][k]; s1 += v; s2 += v * v; }
        const float m = s1 * (1.0f / D);
        const float var = s2 * (1.0f / D) - m * m;
        mu[c] = m; rstd[c] = rsqrtf(var + EPS);
    }
    __syncthreads();
    #pragma unroll
    for (int r = 0; r < 16; ++r)
        out[(size_t)(rowBase + r) * D + c] = (ys[r][c] - mu[r]) * rstd[r];
}

// ---------------- launch ----------------
extern "C" void kernel_launch(void* const* d_in, const int* in_sizes, int n_in,
                              void* d_out, int out_size) {
    const float* inQ = (const float*)d_in[0];
    const float* inK = (const float*)d_in[1];
    const float* inV = (const float*)d_in[2];
    const int*   mask = (const int*)d_in[3];      // bool stored as 4-byte (proven R7)
    const float* W0 = (const float*)d_in[4];
    const float* Wq = (const float*)d_in[5];
    const float* Wk = (const float*)d_in[6];
    const float* Wv = (const float*)d_in[7];
    const float* Wo = (const float*)d_in[8];
    float* out = (float*)d_out;

    float *resid_p, *Q_p, *K_p, *V_p, *ctx_p, *sc_p;
    cudaGetSymbolAddress((void**)&resid_p, g_resid);
    cudaGetSymbolAddress((void**)&Q_p, g_Q);
    cudaGetSymbolAddress((void**)&K_p, g_K);
    cudaGetSymbolAddress((void**)&V_p, g_V);
    cudaGetSymbolAddress((void**)&ctx_p, g_ctx);
    cudaGetSymbolAddress((void**)&sc_p, g_scores);

    const size_t normElems = (size_t)RT * D;                 // 2,097,152
    const size_t attnElems = (size_t)B * H * S * S;          // 134,217,728
    const int attnInOut = ((size_t)out_size >= normElems + attnElems);
    float* sc = attnInOut ? out + normElems : sc_p;

    // 0) zero the atomic-accumulated ctx
    zero_ctx_kernel<<<RT * D / 4 / 256, 256>>>(ctx_p);

    // 1) all projections, one launch
    proj_all_kernel<<<dim3(RT / 8, 4), 128>>>(inQ, inK, inV, W0, Wq, Wk, Wv,
                                              resid_p, Q_p, K_p, V_p);

    // 2) e = exp(scores - tilemax) + per-tile (max, expsum) partials
    scores_kernel<<<dim3(16, 16, 32), 256>>>(Q_p, K_p, mask, sc);

    // 3) row stats (max + inverse sum)
    rowstat_kernel<<<256, 256>>>();

    // 4) k-partitioned normalize + attn write + partial PV (atomic ctx)
    pv_kernel<<<dim3(32, 32, 32), 256>>>(sc, V_p, ctx_p, attnInOut);

    // 5) output proj + residual + layernorm
    out_kernel<<<RT / 16, 128>>>(Wo, out);
}

// round 14
// speedup vs baseline: 1.5243x; 1.1826x over previous
#include <cuda_runtime.h>
#include <math.h>
#include <stdint.h>

#define B 8
#define S 2048
#define D 128
#define H 4
#define DK 32
#define RT (B*S)          // 16384 rows
#define EPS 1e-5f

// TF32 rounding for mma.sync input registers
__device__ __forceinline__ float tf32r(float x) {
    float y;
    asm("cvt.rna.tf32.f32 %0, %1;" : "=f"(y) : "f"(x));
    return y;
}

// ---------------- scratch (static __device__ globals; no allocation) ----------------
__device__ float g_resid[RT * D];                 // [B*S, D]
__device__ float g_Q[RT * D];                     // [B,H,S,DK]
__device__ float g_K[RT * D];                     // [B,H,S,DK]
__device__ float g_V[RT * D];                     // [B,H,S,DK]
__device__ float g_ctx[RT * D];                   // [B,S,H*DK]
__device__ float g_part[32 * 16 * S];             // per-(bh,ktile128,q) tile max
__device__ float g_psum[32 * 16 * S];             // per-(bh,ktile128,q) sum exp(x - tilemax)
__device__ float g_rowmax[32 * S];                // per-(bh,q) row max
__device__ float g_rowinv[32 * S];                // per-(bh,q) 1/rowsum
__device__ float g_scores[134217728];             // [B,H,S,S] fallback if attn not in d_out

// ---------------- zero ctx (atomic accumulation target) ----------------
__global__ void zero_ctx_kernel(float* __restrict__ ctx) {
    const int i = blockIdx.x * 256 + threadIdx.x;
    ((float4*)ctx)[i] = make_float4(0.f, 0.f, 0.f, 0.f);
}

// ---------------- all 4 projections in one launch: blockIdx.y selects ----------------
__global__ __launch_bounds__(128) void proj_all_kernel(
        const float* __restrict__ inQ, const float* __restrict__ inK,
        const float* __restrict__ inV,
        const float* __restrict__ W0, const float* __restrict__ Wq,
        const float* __restrict__ Wk, const float* __restrict__ Wv,
        float* __restrict__ resid, float* __restrict__ Qo,
        float* __restrict__ Ko, float* __restrict__ Vo) {
    const float* X; const float* W; float* out; int headSplit;
    switch (blockIdx.y) {
        case 0: X = inQ; W = W0; out = resid; headSplit = 0; break;
        case 1: X = inQ; W = Wq; out = Qo;    headSplit = 1; break;
        case 2: X = inK; W = Wk; out = Ko;    headSplit = 1; break;
        default:X = inV; W = Wv; out = Vo;    headSplit = 1; break;
    }
    __shared__ float xs[8][128];
    const int rowBase = blockIdx.x * 8;
    const int c = threadIdx.x;
    #pragma unroll
    for (int r = 0; r < 8; ++r)
        xs[r][c] = X[(size_t)(rowBase + r) * D + c];
    __syncthreads();

    float acc[8];
    #pragma unroll
    for (int r = 0; r < 8; ++r) acc[r] = 0.f;
    for (int k = 0; k < D; ++k) {
        float w = W[k * D + c];
        #pragma unroll
        for (int r = 0; r < 8; ++r)
            acc[r] = fmaf(xs[r][k], w, acc[r]);
    }

    if (!headSplit) {
        #pragma unroll
        for (int r = 0; r < 8; ++r)
            out[(size_t)(rowBase + r) * D + c] = acc[r];
    } else {
        const int h = c >> 5, d = c & 31;
        #pragma unroll
        for (int r = 0; r < 8; ++r) {
            const int row = rowBase + r;
            const int b = row / S, s = row % S;
            out[(((size_t)(b * H + h)) * S + s) * DK + d] = acc[r];
        }
    }
}

// ---------------- scores via mma.sync TF32: e = exp(masked/scaled QK^T - tilemax) -----
// grid (kt=16, qt=16, bh=32), 256 threads (8 warps). Warp = 16 q-rows x 128 k-cols.
// m16n8k8 fragments; K=32 in 4 k-steps; per-128-tile (max, expsum) partials.
__global__ __launch_bounds__(256, 2) void scores_mma_kernel(
        const float* __restrict__ Q, const float* __restrict__ K,
        const int* __restrict__ mask, float* __restrict__ sc) {
    const int kt = blockIdx.x, qt = blockIdx.y, bh = blockIdx.z;
    const int b = bh >> 2;                        // bh = b*H + h
    __shared__ float qs[128][36];                 // pad 36: conflict-free frag gathers
    __shared__ float ks[128][36];
    const int tid = threadIdx.x;
    const int w = tid >> 5, lane = tid & 31;
    const int gid = lane >> 2, tig = lane & 3;    // fragment coords

    // load Q,K tiles (fp32 -> tf32-rounded)
    const float4* Qb = (const float4*)(Q + ((size_t)bh * S + (size_t)qt * 128) * DK);
    const float4* Kb = (const float4*)(K + ((size_t)bh * S + (size_t)kt * 128) * DK);
    for (int f = tid; f < 1024; f += 256) {       // 128 rows * 8 float4
        const int row = f >> 3, sg = (f & 7) * 4;
        float4 v = Qb[f];
        qs[row][sg] = tf32r(v.x); qs[row][sg+1] = tf32r(v.y);
        qs[row][sg+2] = tf32r(v.z); qs[row][sg+3] = tf32r(v.w);
        v = Kb[f];
        ks[row][sg] = tf32r(v.x); ks[row][sg+1] = tf32r(v.y);
        ks[row][sg+2] = tf32r(v.z); ks[row][sg+3] = tf32r(v.w);
    }
    __syncthreads();

    const int tq = w * 16;
    float c[16][4];
    #pragma unroll
    for (int nb = 0; nb < 16; ++nb) { c[nb][0]=0.f; c[nb][1]=0.f; c[nb][2]=0.f; c[nb][3]=0.f; }

    // preload A fragments for all 4 k-steps (a0:(gid,tig) a1:(gid+8,tig) a2:(gid,tig+4) a3:(gid+8,tig+4))
    uint32_t a[4][4];
    #pragma unroll
    for (int ksi = 0; ksi < 4; ++ksi) {
        const int k8 = ksi * 8;
        a[ksi][0] = __float_as_uint(qs[tq + gid    ][k8 + tig]);
        a[ksi][1] = __float_as_uint(qs[tq + gid + 8][k8 + tig]);
        a[ksi][2] = __float_as_uint(qs[tq + gid    ][k8 + tig + 4]);
        a[ksi][3] = __float_as_uint(qs[tq + gid + 8][k8 + tig + 4]);
    }
    #pragma unroll
    for (int nb = 0; nb < 16; ++nb) {
        const int nrow = nb * 8 + gid;            // key index for this lane's B column
        #pragma unroll
        for (int ksi = 0; ksi < 4; ++ksi) {
            const int k8 = ksi * 8;
            const uint32_t b0 = __float_as_uint(ks[nrow][k8 + tig]);
            const uint32_t b1 = __float_as_uint(ks[nrow][k8 + tig + 4]);
            asm volatile(
                "mma.sync.aligned.m16n8k8.row.col.f32.tf32.tf32.f32 "
                "{%0,%1,%2,%3}, {%4,%5,%6,%7}, {%8,%9}, {%0,%1,%2,%3};"
                : "+f"(c[nb][0]), "+f"(c[nb][1]), "+f"(c[nb][2]), "+f"(c[nb][3])
                : "r"(a[ksi][0]), "r"(a[ksi][1]), "r"(a[ksi][2]), "r"(a[ksi][3]),
                  "r"(b0), "r"(b1));
        }
    }

    // epilogue: scale + mask; per-row (r0 = tq+gid, r1 = r0+8) tile max / expsum
    const float scale = 0.17677669529663687f;     // 1/sqrt(32)
    const int r0 = qt * 128 + tq + gid, r1 = r0 + 8;
    const int colb = kt * 128 + 2 * tig;
    const int* mp0 = mask + ((size_t)b * S + r0) * S + colb;
    const int* mp1 = mask + ((size_t)b * S + r1) * S + colb;
    float mx0 = -INFINITY, mx1 = -INFINITY;
    #pragma unroll
    for (int nb = 0; nb < 16; ++nb) {
        const int2 m0 = *(const int2*)(mp0 + nb * 8);
        const int2 m1 = *(const int2*)(mp1 + nb * 8);
        c[nb][0] = m0.x ? -1e9f : c[nb][0] * scale;
        c[nb][1] = m0.y ? -1e9f : c[nb][1] * scale;
        c[nb][2] = m1.x ? -1e9f : c[nb][2] * scale;
        c[nb][3] = m1.y ? -1e9f : c[nb][3] * scale;
        mx0 = fmaxf(mx0, fmaxf(c[nb][0], c[nb][1]));
        mx1 = fmaxf(mx1, fmaxf(c[nb][2], c[nb][3]));
    }
    // reduce across the 4 lanes sharing gid (tig = lane&3 -> xor 1,2)
    mx0 = fmaxf(mx0, __shfl_xor_sync(0xffffffffu, mx0, 1));
    mx0 = fmaxf(mx0, __shfl_xor_sync(0xffffffffu, mx0, 2));
    mx1 = fmaxf(mx1, __shfl_xor_sync(0xffffffffu, mx1, 1));
    mx1 = fmaxf(mx1, __shfl_xor_sync(0xffffffffu, mx1, 2));

    float es0 = 0.f, es1 = 0.f;
    #pragma unroll
    for (int nb = 0; nb < 16; ++nb) {
        c[nb][0] = __expf(c[nb][0] - mx0); es0 += c[nb][0];
        c[nb][1] = __expf(c[nb][1] - mx0); es0 += c[nb][1];
        c[nb][2] = __expf(c[nb][2] - mx1); es1 += c[nb][2];
        c[nb][3] = __expf(c[nb][3] - mx1); es1 += c[nb][3];
    }
    es0 += __shfl_xor_sync(0xffffffffu, es0, 1);
    es0 += __shfl_xor_sync(0xffffffffu, es0, 2);
    es1 += __shfl_xor_sync(0xffffffffu, es1, 1);
    es1 += __shfl_xor_sync(0xffffffffu, es1, 2);

    // store e (float2 per (row, nb); 4 lanes cover a 32B sector per row-block)
    float* s0 = sc + ((size_t)bh * S + r0) * S + colb;
    float* s1 = sc + ((size_t)bh * S + r1) * S + colb;
    #pragma unroll
    for (int nb = 0; nb < 16; ++nb) {
        *(float2*)(s0 + nb * 8) = make_float2(c[nb][0], c[nb][1]);
        *(float2*)(s1 + nb * 8) = make_float2(c[nb][2], c[nb][3]);
    }
    if (tig == 0) {
        const size_t i0 = ((size_t)bh * 16 + kt) * S + r0;
        const size_t i1 = ((size_t)bh * 16 + kt) * S + r1;
        g_part[i0] = mx0; g_psum[i0] = es0;
        g_part[i1] = mx1; g_psum[i1] = es1;
    }
}

// ---------------- row stats: combine 16 tile partials -> rowmax + 1/rowsum ----------
__global__ void rowstat_kernel() {
    const int idx = blockIdx.x * 256 + threadIdx.x;   // 0..65535
    const int bh = idx >> 11, q = idx & 2047;
    float m = -INFINITY;
    #pragma unroll
    for (int kt = 0; kt < 16; ++kt)
        m = fmaxf(m, g_part[((size_t)bh * 16 + kt) * S + q]);
    float s = 0.f;
    #pragma unroll
    for (int kt = 0; kt < 16; ++kt) {
        const size_t i = ((size_t)bh * 16 + kt) * S + q;
        s += g_psum[i] * __expf(g_part[i] - m);
    }
    g_rowmax[idx] = m;
    g_rowinv[idx] = 1.0f / s;
}

// ---------------- k-partitioned attn-normalize + partial PV ----------------
// grid (kt=32, qt=32, bh=32); block: one 64q x 64k tile; accumulates ctx via atomics.
__global__ __launch_bounds__(256, 4) void pv_kernel(
        float* __restrict__ sc, const float* __restrict__ V,
        float* __restrict__ ctx, int writeAttn) {
    const int kt = blockIdx.x, qt = blockIdx.y, bh = blockIdx.z;
    const int b = bh >> 2, h = bh & 3;
    __shared__ float as_t[64][68];                // attn transposed [k][q]
    __shared__ float vs[64][32];                  // [k][d]
    __shared__ float fac[64];                     // exp(tilemax - rowmax) / rowsum
    const int tid = threadIdx.x;

    if (tid < 64) {
        const int q = qt * 64 + tid;
        const float mt = g_part[((size_t)bh * 16 + (kt >> 1)) * S + q];
        fac[tid] = __expf(mt - g_rowmax[bh * S + q]) * g_rowinv[bh * S + q];
    }
    __syncthreads();

    for (int f = tid; f < 1024; f += 256) {       // 64 rows * 16 float4
        const int row = f >> 4, sg = (f & 15) * 4;
        const size_t gidx = (((size_t)bh * S + qt * 64 + row) * S + (size_t)kt * 64 + sg) >> 2;
        float4 x = ((const float4*)sc)[gidx];
        const float fv = fac[row];
        x.x *= fv; x.y *= fv; x.z *= fv; x.w *= fv;
        if (writeAttn) ((float4*)sc)[gidx] = x;
        as_t[sg + 0][row] = x.x;
        as_t[sg + 1][row] = x.y;
        as_t[sg + 2][row] = x.z;
        as_t[sg + 3][row] = x.w;
    }
    const float4* vb = (const float4*)(V + ((size_t)bh * S + (size_t)kt * 64) * DK);
    for (int f = tid; f < 512; f += 256)
        ((float4*)vs)[f] = vb[f];
    __syncthreads();

    const int d  = tid & 31;
    const int qg = (tid >> 5) * 8;
    float acc[8] = {};
    for (int kk = 0; kk < 64; ++kk) {
        const float v = vs[kk][d];
        const float4 a0 = *(const float4*)&as_t[kk][qg];
        const float4 a1 = *(const float4*)&as_t[kk][qg + 4];
        acc[0] = fmaf(a0.x, v, acc[0]);
        acc[1] = fmaf(a0.y, v, acc[1]);
        acc[2] = fmaf(a0.z, v, acc[2]);
        acc[3] = fmaf(a0.w, v, acc[3]);
        acc[4] = fmaf(a1.x, v, acc[4]);
        acc[5] = fmaf(a1.y, v, acc[5]);
        acc[6] = fmaf(a1.z, v, acc[6]);
        acc[7] = fmaf(a1.w, v, acc[7]);
    }
    #pragma unroll
    for (int i = 0; i < 8; ++i)
        atomicAdd(&ctx[((size_t)b * S + qt * 64 + qg + i) * D + h * DK + d], acc[i]);
}

// ---------------- final: y = ctx @ Wo + resid; out = layernorm(y) ----------------
__global__ __launch_bounds__(128) void out_kernel(const float* __restrict__ Wo,
                                                  float* __restrict__ out) {
    __shared__ float xs[16][128];
    __shared__ float ys[16][129];
    __shared__ float mu[16], rstd[16];
    const int rowBase = blockIdx.x * 16;
    const int c = threadIdx.x;

    #pragma unroll
    for (int r = 0; r < 16; ++r)
        xs[r][c] = g_ctx[(size_t)(rowBase + r) * D + c];
    __syncthreads();

    float acc[16];
    #pragma unroll
    for (int r = 0; r < 16; ++r)
        acc[r] = g_resid[(size_t)(rowBase + r) * D + c];
    for (int k = 0; k < D; ++k) {
        float w = Wo[k * D + c];
        #pragma unroll
        for (int r = 0; r < 16; ++r)
            acc[r] = fmaf(xs[r][k], w, acc[r]);
    }
    #pragma unroll
    for (int r = 0; r < 16; ++r) ys[r][c] = acc[r];
    __syncthreads();

    if (c < 16) {
        float s1 = 0.f, s2 = 0.f;
        for (int k = 0; k < D; ++k) { float v = ys[c][k]; s1 += v; s2 += v * v; }
        const float m = s1 * (1.0f / D);
        const float var = s2 * (1.0f / D) - m * m;
        mu[c] = m; rstd[c] = rsqrtf(var + EPS);
    }
    __syncthreads();
    #pragma unroll
    for (int r = 0; r < 16; ++r)
        out[(size_t)(rowBase + r) * D + c] = (ys[r][c] - mu[r]) * rstd[r];
}

// ---------------- launch ----------------
extern "C" void kernel_launch(void* const* d_in, const int* in_sizes, int n_in,
                              void* d_out, int out_size) {
    const float* inQ = (const float*)d_in[0];
    const float* inK = (const float*)d_in[1];
    const float* inV = (const float*)d_in[2];
    const int*   mask = (const int*)d_in[3];      // bool stored as 4-byte (proven R7)
    const float* W0 = (const float*)d_in[4];
    const float* Wq = (const float*)d_in[5];
    const float* Wk = (const float*)d_in[6];
    const float* Wv = (const float*)d_in[7];
    const float* Wo = (const float*)d_in[8];
    float* out = (float*)d_out;

    float *resid_p, *Q_p, *K_p, *V_p, *ctx_p, *sc_p;
    cudaGetSymbolAddress((void**)&resid_p, g_resid);
    cudaGetSymbolAddress((void**)&Q_p, g_Q);
    cudaGetSymbolAddress((void**)&K_p, g_K);
    cudaGetSymbolAddress((void**)&V_p, g_V);
    cudaGetSymbolAddress((void**)&ctx_p, g_ctx);
    cudaGetSymbolAddress((void**)&sc_p, g_scores);

    const size_t normElems = (size_t)RT * D;                 // 2,097,152
    const size_t attnElems = (size_t)B * H * S * S;          // 134,217,728
    const int attnInOut = ((size_t)out_size >= normElems + attnElems);
    float* sc = attnInOut ? out + normElems : sc_p;

    // 0) zero the atomic-accumulated ctx
    zero_ctx_kernel<<<RT * D / 4 / 256, 256>>>(ctx_p);

    // 1) all projections, one launch
    proj_all_kernel<<<dim3(RT / 8, 4), 128>>>(inQ, inK, inV, W0, Wq, Wk, Wv,
                                              resid_p, Q_p, K_p, V_p);

    // 2) mma.sync TF32 QK^T -> e = exp(x - tilemax) + per-tile (max, expsum)
    scores_mma_kernel<<<dim3(16, 16, 32), 256>>>(Q_p, K_p, mask, sc);

    // 3) row stats (max + inverse sum)
    rowstat_kernel<<<256, 256>>>();

    // 4) k-partitioned normalize + attn write + partial PV (atomic ctx)
    pv_kernel<<<dim3(32, 32, 32), 256>>>(sc, V_p, ctx_p, attnInOut);

    // 5) output proj + residual + layernorm
    out_kernel<<<RT / 16, 128>>>(Wo, out);
}

// round 15
// speedup vs baseline: 1.5244x; 1.0001x over previous
#include <cuda_runtime.h>
#include <math.h>
#include <stdint.h>

#define B 8
#define S 2048
#define D 128
#define H 4
#define DK 32
#define RT (B*S)          // 16384 rows
#define EPS 1e-5f

// TF32 rounding for mma.sync input registers
__device__ __forceinline__ float tf32r(float x) {
    float y;
    asm("cvt.rna.tf32.f32 %0, %1;" : "=f"(y) : "f"(x));
    return y;
}

// ---------------- scratch (static __device__ globals; no allocation) ----------------
__device__ float g_resid[RT * D];                 // [B*S, D]
__device__ float g_Q[RT * D];                     // [B,H,S,DK]
__device__ float g_K[RT * D];                     // [B,H,S,DK]
__device__ float g_V[RT * D];                     // [B,H,S,DK]
__device__ float g_ctx[RT * D];                   // [B,S,H*DK]
__device__ float g_part[32 * 16 * S];             // per-(bh,ktile128,q) tile max
__device__ float g_psum[32 * 16 * S];             // per-(bh,ktile128,q) sum exp(x - tilemax)
__device__ float g_rowmax[32 * S];                // per-(bh,q) row max
__device__ float g_rowinv[32 * S];                // per-(bh,q) 1/rowsum
__device__ float g_scores[134217728];             // [B,H,S,S] fallback if attn not in d_out

// ---------------- zero ctx (atomic accumulation target) ----------------
__global__ void zero_ctx_kernel(float* __restrict__ ctx) {
    const int i = blockIdx.x * 256 + threadIdx.x;
    ((float4*)ctx)[i] = make_float4(0.f, 0.f, 0.f, 0.f);
}

// ---------------- all 4 projections in one launch: blockIdx.y selects ----------------
__global__ __launch_bounds__(128) void proj_all_kernel(
        const float* __restrict__ inQ, const float* __restrict__ inK,
        const float* __restrict__ inV,
        const float* __restrict__ W0, const float* __restrict__ Wq,
        const float* __restrict__ Wk, const float* __restrict__ Wv,
        float* __restrict__ resid, float* __restrict__ Qo,
        float* __restrict__ Ko, float* __restrict__ Vo) {
    const float* X; const float* W; float* out; int headSplit;
    switch (blockIdx.y) {
        case 0: X = inQ; W = W0; out = resid; headSplit = 0; break;
        case 1: X = inQ; W = Wq; out = Qo;    headSplit = 1; break;
        case 2: X = inK; W = Wk; out = Ko;    headSplit = 1; break;
        default:X = inV; W = Wv; out = Vo;    headSplit = 1; break;
    }
    __shared__ float xs[8][128];
    const int rowBase = blockIdx.x * 8;
    const int c = threadIdx.x;
    #pragma unroll
    for (int r = 0; r < 8; ++r)
        xs[r][c] = X[(size_t)(rowBase + r) * D + c];
    __syncthreads();

    float acc[8];
    #pragma unroll
    for (int r = 0; r < 8; ++r) acc[r] = 0.f;
    for (int k = 0; k < D; ++k) {
        float w = W[k * D + c];
        #pragma unroll
        for (int r = 0; r < 8; ++r)
            acc[r] = fmaf(xs[r][k], w, acc[r]);
    }

    if (!headSplit) {
        #pragma unroll
        for (int r = 0; r < 8; ++r)
            out[(size_t)(rowBase + r) * D + c] = acc[r];
    } else {
        const int h = c >> 5, d = c & 31;
        #pragma unroll
        for (int r = 0; r < 8; ++r) {
            const int row = rowBase + r;
            const int b = row / S, s = row % S;
            out[(((size_t)(b * H + h)) * S + s) * DK + d] = acc[r];
        }
    }
}

// ---------------- scores via mma.sync TF32: e = exp(masked/scaled QK^T - tilemax) -----
// grid (kt=16, qt=16, bh=32), 256 threads (8 warps). Warp = 16 q-rows x 128 k-cols.
// m16n8k8 fragments; K=32 in 4 k-steps; per-128-tile (max, expsum) partials.
__global__ __launch_bounds__(256, 2) void scores_mma_kernel(
        const float* __restrict__ Q, const float* __restrict__ K,
        const int* __restrict__ mask, float* __restrict__ sc) {
    const int kt = blockIdx.x, qt = blockIdx.y, bh = blockIdx.z;
    const int b = bh >> 2;                        // bh = b*H + h
    __shared__ float qs[128][36];                 // pad 36: conflict-free frag gathers
    __shared__ float ks[128][36];
    const int tid = threadIdx.x;
    const int w = tid >> 5, lane = tid & 31;
    const int gid = lane >> 2, tig = lane & 3;    // fragment coords

    // load Q,K tiles (fp32 -> tf32-rounded)
    const float4* Qb = (const float4*)(Q + ((size_t)bh * S + (size_t)qt * 128) * DK);
    const float4* Kb = (const float4*)(K + ((size_t)bh * S + (size_t)kt * 128) * DK);
    for (int f = tid; f < 1024; f += 256) {       // 128 rows * 8 float4
        const int row = f >> 3, sg = (f & 7) * 4;
        float4 v = Qb[f];
        qs[row][sg] = tf32r(v.x); qs[row][sg+1] = tf32r(v.y);
        qs[row][sg+2] = tf32r(v.z); qs[row][sg+3] = tf32r(v.w);
        v = Kb[f];
        ks[row][sg] = tf32r(v.x); ks[row][sg+1] = tf32r(v.y);
        ks[row][sg+2] = tf32r(v.z); ks[row][sg+3] = tf32r(v.w);
    }
    __syncthreads();

    const int tq = w * 16;
    float c[16][4];
    #pragma unroll
    for (int nb = 0; nb < 16; ++nb) { c[nb][0]=0.f; c[nb][1]=0.f; c[nb][2]=0.f; c[nb][3]=0.f; }

    // preload A fragments for all 4 k-steps (a0:(gid,tig) a1:(gid+8,tig) a2:(gid,tig+4) a3:(gid+8,tig+4))
    uint32_t a[4][4];
    #pragma unroll
    for (int ksi = 0; ksi < 4; ++ksi) {
        const int k8 = ksi * 8;
        a[ksi][0] = __float_as_uint(qs[tq + gid    ][k8 + tig]);
        a[ksi][1] = __float_as_uint(qs[tq + gid + 8][k8 + tig]);
        a[ksi][2] = __float_as_uint(qs[tq + gid    ][k8 + tig + 4]);
        a[ksi][3] = __float_as_uint(qs[tq + gid + 8][k8 + tig + 4]);
    }
    #pragma unroll
    for (int nb = 0; nb < 16; ++nb) {
        const int nrow = nb * 8 + gid;            // key index for this lane's B column
        #pragma unroll
        for (int ksi = 0; ksi < 4; ++ksi) {
            const int k8 = ksi * 8;
            const uint32_t b0 = __float_as_uint(ks[nrow][k8 + tig]);
            const uint32_t b1 = __float_as_uint(ks[nrow][k8 + tig + 4]);
            asm volatile(
                "mma.sync.aligned.m16n8k8.row.col.f32.tf32.tf32.f32 "
                "{%0,%1,%2,%3}, {%4,%5,%6,%7}, {%8,%9}, {%0,%1,%2,%3};"
                : "+f"(c[nb][0]), "+f"(c[nb][1]), "+f"(c[nb][2]), "+f"(c[nb][3])
                : "r"(a[ksi][0]), "r"(a[ksi][1]), "r"(a[ksi][2]), "r"(a[ksi][3]),
                  "r"(b0), "r"(b1));
        }
    }

    // epilogue: scale + mask; per-row (r0 = tq+gid, r1 = r0+8) tile max / expsum
    const float scale = 0.17677669529663687f;     // 1/sqrt(32)
    const int r0 = qt * 128 + tq + gid, r1 = r0 + 8;
    const int colb = kt * 128 + 2 * tig;
    const int* mp0 = mask + ((size_t)b * S + r0) * S + colb;
    const int* mp1 = mask + ((size_t)b * S + r1) * S + colb;
    float mx0 = -INFINITY, mx1 = -INFINITY;
    #pragma unroll
    for (int nb = 0; nb < 16; ++nb) {
        const int2 m0 = *(const int2*)(mp0 + nb * 8);
        const int2 m1 = *(const int2*)(mp1 + nb * 8);
        c[nb][0] = m0.x ? -1e9f : c[nb][0] * scale;
        c[nb][1] = m0.y ? -1e9f : c[nb][1] * scale;
        c[nb][2] = m1.x ? -1e9f : c[nb][2] * scale;
        c[nb][3] = m1.y ? -1e9f : c[nb][3] * scale;
        mx0 = fmaxf(mx0, fmaxf(c[nb][0], c[nb][1]));
        mx1 = fmaxf(mx1, fmaxf(c[nb][2], c[nb][3]));
    }
    // reduce across the 4 lanes sharing gid (tig = lane&3 -> xor 1,2)
    mx0 = fmaxf(mx0, __shfl_xor_sync(0xffffffffu, mx0, 1));
    mx0 = fmaxf(mx0, __shfl_xor_sync(0xffffffffu, mx0, 2));
    mx1 = fmaxf(mx1, __shfl_xor_sync(0xffffffffu, mx1, 1));
    mx1 = fmaxf(mx1, __shfl_xor_sync(0xffffffffu, mx1, 2));

    float es0 = 0.f, es1 = 0.f;
    #pragma unroll
    for (int nb = 0; nb < 16; ++nb) {
        c[nb][0] = __expf(c[nb][0] - mx0); es0 += c[nb][0];
        c[nb][1] = __expf(c[nb][1] - mx0); es0 += c[nb][1];
        c[nb][2] = __expf(c[nb][2] - mx1); es1 += c[nb][2];
        c[nb][3] = __expf(c[nb][3] - mx1); es1 += c[nb][3];
    }
    es0 += __shfl_xor_sync(0xffffffffu, es0, 1);
    es0 += __shfl_xor_sync(0xffffffffu, es0, 2);
    es1 += __shfl_xor_sync(0xffffffffu, es1, 1);
    es1 += __shfl_xor_sync(0xffffffffu, es1, 2);

    // store e (float2 per (row, nb); 4 lanes cover a 32B sector per row-block)
    float* s0 = sc + ((size_t)bh * S + r0) * S + colb;
    float* s1 = sc + ((size_t)bh * S + r1) * S + colb;
    #pragma unroll
    for (int nb = 0; nb < 16; ++nb) {
        *(float2*)(s0 + nb * 8) = make_float2(c[nb][0], c[nb][1]);
        *(float2*)(s1 + nb * 8) = make_float2(c[nb][2], c[nb][3]);
    }
    if (tig == 0) {
        const size_t i0 = ((size_t)bh * 16 + kt) * S + r0;
        const size_t i1 = ((size_t)bh * 16 + kt) * S + r1;
        g_part[i0] = mx0; g_psum[i0] = es0;
        g_part[i1] = mx1; g_psum[i1] = es1;
    }
}

// ---------------- row stats: combine 16 tile partials -> rowmax + 1/rowsum ----------
__global__ void rowstat_kernel() {
    const int idx = blockIdx.x * 256 + threadIdx.x;   // 0..65535
    const int bh = idx >> 11, q = idx & 2047;
    float m = -INFINITY;
    #pragma unroll
    for (int kt = 0; kt < 16; ++kt)
        m = fmaxf(m, g_part[((size_t)bh * 16 + kt) * S + q]);
    float s = 0.f;
    #pragma unroll
    for (int kt = 0; kt < 16; ++kt) {
        const size_t i = ((size_t)bh * 16 + kt) * S + q;
        s += g_psum[i] * __expf(g_part[i] - m);
    }
    g_rowmax[idx] = m;
    g_rowinv[idx] = 1.0f / s;
}

// ---------------- k-partitioned attn-normalize + partial PV ----------------
// grid (kt=32, qt=32, bh=32); block: one 64q x 64k tile; accumulates ctx via atomics.
__global__ __launch_bounds__(256, 4) void pv_kernel(
        float* __restrict__ sc, const float* __restrict__ V,
        float* __restrict__ ctx, int writeAttn) {
    const int kt = blockIdx.x, qt = blockIdx.y, bh = blockIdx.z;
    const int b = bh >> 2, h = bh & 3;
    __shared__ float as_t[64][68];                // attn transposed [k][q]
    __shared__ float vs[64][32];                  // [k][d]
    __shared__ float fac[64];                     // exp(tilemax - rowmax) / rowsum
    const int tid = threadIdx.x;

    if (tid < 64) {
        const int q = qt * 64 + tid;
        const float mt = g_part[((size_t)bh * 16 + (kt >> 1)) * S + q];
        fac[tid] = __expf(mt - g_rowmax[bh * S + q]) * g_rowinv[bh * S + q];
    }
    __syncthreads();

    for (int f = tid; f < 1024; f += 256) {       // 64 rows * 16 float4
        const int row = f >> 4, sg = (f & 15) * 4;
        const size_t gidx = (((size_t)bh * S + qt * 64 + row) * S + (size_t)kt * 64 + sg) >> 2;
        float4 x = ((const float4*)sc)[gidx];
        const float fv = fac[row];
        x.x *= fv; x.y *= fv; x.z *= fv; x.w *= fv;
        if (writeAttn) ((float4*)sc)[gidx] = x;
        as_t[sg + 0][row] = x.x;
        as_t[sg + 1][row] = x.y;
        as_t[sg + 2][row] = x.z;
        as_t[sg + 3][row] = x.w;
    }
    const float4* vb = (const float4*)(V + ((size_t)bh * S + (size_t)kt * 64) * DK);
    for (int f = tid; f < 512; f += 256)
        ((float4*)vs)[f] = vb[f];
    __syncthreads();

    const int d  = tid & 31;
    const int qg = (tid >> 5) * 8;
    float acc[8] = {};
    for (int kk = 0; kk < 64; ++kk) {
        const float v = vs[kk][d];
        const float4 a0 = *(const float4*)&as_t[kk][qg];
        const float4 a1 = *(const float4*)&as_t[kk][qg + 4];
        acc[0] = fmaf(a0.x, v, acc[0]);
        acc[1] = fmaf(a0.y, v, acc[1]);
        acc[2] = fmaf(a0.z, v, acc[2]);
        acc[3] = fmaf(a0.w, v, acc[3]);
        acc[4] = fmaf(a1.x, v, acc[4]);
        acc[5] = fmaf(a1.y, v, acc[5]);
        acc[6] = fmaf(a1.z, v, acc[6]);
        acc[7] = fmaf(a1.w, v, acc[7]);
    }
    #pragma unroll
    for (int i = 0; i < 8; ++i)
        atomicAdd(&ctx[((size_t)b * S + qt * 64 + qg + i) * D + h * DK + d], acc[i]);
}

// ---------------- final: y = ctx @ Wo + resid; out = layernorm(y) ----------------
__global__ __launch_bounds__(128) void out_kernel(const float* __restrict__ Wo,
                                                  float* __restrict__ out) {
    __shared__ float xs[16][128];
    __shared__ float ys[16][129];
    __shared__ float mu[16], rstd[16];
    const int rowBase = blockIdx.x * 16;
    const int c = threadIdx.x;

    #pragma unroll
    for (int r = 0; r < 16; ++r)
        xs[r][c] = g_ctx[(size_t)(rowBase + r) * D + c];
    __syncthreads();

    float acc[16];
    #pragma unroll
    for (int r = 0; r < 16; ++r)
        acc[r] = g_resid[(size_t)(rowBase + r) * D + c];
    for (int k = 0; k < D; ++k) {
        float w = Wo[k * D + c];
        #pragma unroll
        for (int r = 0; r < 16; ++r)
            acc[r] = fmaf(xs[r][k], w, acc[r]);
    }
    #pragma unroll
    for (int r = 0; r < 16; ++r) ys[r][c] = acc[r];
    __syncthreads();

    if (c < 16) {
        float s1 = 0.f, s2 = 0.f;
        for (int k = 0; k < D; ++k) { float v = ys[c][k]; s1 += v; s2 += v * v; }
        const float m = s1 * (1.0f / D);
        const float var = s2 * (1.0f / D) - m * m;
        mu[c] = m; rstd[c] = rsqrtf(var + EPS);
    }
    __syncthreads();
    #pragma unroll
    for (int r = 0; r < 16; ++r)
        out[(size_t)(rowBase + r) * D + c] = (ys[r][c] - mu[r]) * rstd[r];
}

// ---------------- launch ----------------
extern "C" void kernel_launch(void* const* d_in, const int* in_sizes, int n_in,
                              void* d_out, int out_size) {
    const float* inQ = (const float*)d_in[0];
    const float* inK = (const float*)d_in[1];
    const float* inV = (const float*)d_in[2];
    const int*   mask = (const int*)d_in[3];      // bool stored as 4-byte (proven R7)
    const float* W0 = (const float*)d_in[4];
    const float* Wq = (const float*)d_in[5];
    const float* Wk = (const float*)d_in[6];
    const float* Wv = (const float*)d_in[7];
    const float* Wo = (const float*)d_in[8];
    float* out = (float*)d_out;

    float *resid_p, *Q_p, *K_p, *V_p, *ctx_p, *sc_p;
    cudaGetSymbolAddress((void**)&resid_p, g_resid);
    cudaGetSymbolAddress((void**)&Q_p, g_Q);
    cudaGetSymbolAddress((void**)&K_p, g_K);
    cudaGetSymbolAddress((void**)&V_p, g_V);
    cudaGetSymbolAddress((void**)&ctx_p, g_ctx);
    cudaGetSymbolAddress((void**)&sc_p, g_scores);

    const size_t normElems = (size_t)RT * D;                 // 2,097,152
    const size_t attnElems = (size_t)B * H * S * S;          // 134,217,728
    const int attnInOut = ((size_t)out_size >= normElems + attnElems);
    float* sc = attnInOut ? out + normElems : sc_p;

    // 0) zero the atomic-accumulated ctx
    zero_ctx_kernel<<<RT * D / 4 / 256, 256>>>(ctx_p);

    // 1) all projections, one launch
    proj_all_kernel<<<dim3(RT / 8, 4), 128>>>(inQ, inK, inV, W0, Wq, Wk, Wv,
                                              resid_p, Q_p, K_p, V_p);

    // 2) mma.sync TF32 QK^T -> e = exp(x - tilemax) + per-tile (max, expsum)
    scores_mma_kernel<<<dim3(16, 16, 32), 256>>>(Q_p, K_p, mask, sc);

    // 3) row stats (max + inverse sum)
    rowstat_kernel<<<256, 256>>>();

    // 4) k-partitioned normalize + attn write + partial PV (atomic ctx)
    pv_kernel<<<dim3(32, 32, 32), 256>>>(sc, V_p, ctx_p, attnInOut);

    // 5) output proj + residual + layernorm
    out_kernel<<<RT / 16, 128>>>(Wo, out);
}

// round 16
// speedup vs baseline: 1.7036x; 1.1176x over previous
#include <cuda_runtime.h>
#include <math.h>
#include <stdint.h>

#define B 8
#define S 2048
#define D 128
#define H 4
#define DK 32
#define RT (B*S)          // 16384 rows
#define EPS 1e-5f

// TF32 rounding for mma.sync input registers
__device__ __forceinline__ float tf32r(float x) {
    float y;
    asm("cvt.rna.tf32.f32 %0, %1;" : "=f"(y) : "f"(x));
    return y;
}

// ---------------- scratch (static __device__ globals; no allocation) ----------------
__device__ float g_resid[RT * D];                 // [B*S, D]
__device__ float g_Q[RT * D];                     // [B,H,S,DK]
__device__ float g_K[RT * D];                     // [B,H,S,DK]
__device__ float g_V[RT * D];                     // [B,H,S,DK]
__device__ float g_ctx[RT * D];                   // [B,S,H*DK]
__device__ float g_part[32 * 16 * S];             // per-(bh,ktile128,q) tile max
__device__ float g_psum[32 * 16 * S];             // per-(bh,ktile128,q) sum exp(x - tilemax)
__device__ float g_rowmax[32 * S];                // per-(bh,q) row max
__device__ float g_rowinv[32 * S];                // per-(bh,q) 1/rowsum
__device__ float g_scores[134217728];             // [B,H,S,S] fallback if attn not in d_out

// ---------------- zero ctx (atomic accumulation target) ----------------
__global__ void zero_ctx_kernel(float* __restrict__ ctx) {
    const int i = blockIdx.x * 256 + threadIdx.x;
    ((float4*)ctx)[i] = make_float4(0.f, 0.f, 0.f, 0.f);
}

// ---------------- all 4 projections in one launch: blockIdx.y selects ----------------
__global__ __launch_bounds__(128) void proj_all_kernel(
        const float* __restrict__ inQ, const float* __restrict__ inK,
        const float* __restrict__ inV,
        const float* __restrict__ W0, const float* __restrict__ Wq,
        const float* __restrict__ Wk, const float* __restrict__ Wv,
        float* __restrict__ resid, float* __restrict__ Qo,
        float* __restrict__ Ko, float* __restrict__ Vo) {
    const float* X; const float* W; float* out; int headSplit;
    switch (blockIdx.y) {
        case 0: X = inQ; W = W0; out = resid; headSplit = 0; break;
        case 1: X = inQ; W = Wq; out = Qo;    headSplit = 1; break;
        case 2: X = inK; W = Wk; out = Ko;    headSplit = 1; break;
        default:X = inV; W = Wv; out = Vo;    headSplit = 1; break;
    }
    __shared__ float xs[8][128];
    const int rowBase = blockIdx.x * 8;
    const int c = threadIdx.x;
    #pragma unroll
    for (int r = 0; r < 8; ++r)
        xs[r][c] = X[(size_t)(rowBase + r) * D + c];
    __syncthreads();

    float acc[8];
    #pragma unroll
    for (int r = 0; r < 8; ++r) acc[r] = 0.f;
    for (int k = 0; k < D; ++k) {
        float w = W[k * D + c];
        #pragma unroll
        for (int r = 0; r < 8; ++r)
            acc[r] = fmaf(xs[r][k], w, acc[r]);
    }

    if (!headSplit) {
        #pragma unroll
        for (int r = 0; r < 8; ++r)
            out[(size_t)(rowBase + r) * D + c] = acc[r];
    } else {
        const int h = c >> 5, d = c & 31;
        #pragma unroll
        for (int r = 0; r < 8; ++r) {
            const int row = rowBase + r;
            const int b = row / S, s = row % S;
            out[(((size_t)(b * H + h)) * S + s) * DK + d] = acc[r];
        }
    }
}

// ---------------- scores via mma.sync TF32: e = exp(masked/scaled QK^T - tilemax) -----
// grid (kt=16, qt=16, bh=32), 256 threads (8 warps). Warp = 16 q-rows x 128 k-cols.
__global__ __launch_bounds__(256, 2) void scores_mma_kernel(
        const float* __restrict__ Q, const float* __restrict__ K,
        const int* __restrict__ mask, float* __restrict__ sc) {
    const int kt = blockIdx.x, qt = blockIdx.y, bh = blockIdx.z;
    const int b = bh >> 2;                        // bh = b*H + h
    __shared__ float qs[128][36];                 // pad 36: conflict-free frag gathers
    __shared__ float ks[128][36];
    const int tid = threadIdx.x;
    const int w = tid >> 5, lane = tid & 31;
    const int gid = lane >> 2, tig = lane & 3;    // fragment coords

    const float4* Qb = (const float4*)(Q + ((size_t)bh * S + (size_t)qt * 128) * DK);
    const float4* Kb = (const float4*)(K + ((size_t)bh * S + (size_t)kt * 128) * DK);
    for (int f = tid; f < 1024; f += 256) {       // 128 rows * 8 float4
        const int row = f >> 3, sg = (f & 7) * 4;
        float4 v = Qb[f];
        qs[row][sg] = tf32r(v.x); qs[row][sg+1] = tf32r(v.y);
        qs[row][sg+2] = tf32r(v.z); qs[row][sg+3] = tf32r(v.w);
        v = Kb[f];
        ks[row][sg] = tf32r(v.x); ks[row][sg+1] = tf32r(v.y);
        ks[row][sg+2] = tf32r(v.z); ks[row][sg+3] = tf32r(v.w);
    }
    __syncthreads();

    const int tq = w * 16;
    float c[16][4];
    #pragma unroll
    for (int nb = 0; nb < 16; ++nb) { c[nb][0]=0.f; c[nb][1]=0.f; c[nb][2]=0.f; c[nb][3]=0.f; }

    uint32_t a[4][4];
    #pragma unroll
    for (int ksi = 0; ksi < 4; ++ksi) {
        const int k8 = ksi * 8;
        a[ksi][0] = __float_as_uint(qs[tq + gid    ][k8 + tig]);
        a[ksi][1] = __float_as_uint(qs[tq + gid + 8][k8 + tig]);
        a[ksi][2] = __float_as_uint(qs[tq + gid    ][k8 + tig + 4]);
        a[ksi][3] = __float_as_uint(qs[tq + gid + 8][k8 + tig + 4]);
    }
    #pragma unroll
    for (int nb = 0; nb < 16; ++nb) {
        const int nrow = nb * 8 + gid;
        #pragma unroll
        for (int ksi = 0; ksi < 4; ++ksi) {
            const int k8 = ksi * 8;
            const uint32_t b0 = __float_as_uint(ks[nrow][k8 + tig]);
            const uint32_t b1 = __float_as_uint(ks[nrow][k8 + tig + 4]);
            asm volatile(
                "mma.sync.aligned.m16n8k8.row.col.f32.tf32.tf32.f32 "
                "{%0,%1,%2,%3}, {%4,%5,%6,%7}, {%8,%9}, {%0,%1,%2,%3};"
                : "+f"(c[nb][0]), "+f"(c[nb][1]), "+f"(c[nb][2]), "+f"(c[nb][3])
                : "r"(a[ksi][0]), "r"(a[ksi][1]), "r"(a[ksi][2]), "r"(a[ksi][3]),
                  "r"(b0), "r"(b1));
        }
    }

    const float scale = 0.17677669529663687f;     // 1/sqrt(32)
    const int r0 = qt * 128 + tq + gid, r1 = r0 + 8;
    const int colb = kt * 128 + 2 * tig;
    const int* mp0 = mask + ((size_t)b * S + r0) * S + colb;
    const int* mp1 = mask + ((size_t)b * S + r1) * S + colb;
    float mx0 = -INFINITY, mx1 = -INFINITY;
    #pragma unroll
    for (int nb = 0; nb < 16; ++nb) {
        const int2 m0 = *(const int2*)(mp0 + nb * 8);
        const int2 m1 = *(const int2*)(mp1 + nb * 8);
        c[nb][0] = m0.x ? -1e9f : c[nb][0] * scale;
        c[nb][1] = m0.y ? -1e9f : c[nb][1] * scale;
        c[nb][2] = m1.x ? -1e9f : c[nb][2] * scale;
        c[nb][3] = m1.y ? -1e9f : c[nb][3] * scale;
        mx0 = fmaxf(mx0, fmaxf(c[nb][0], c[nb][1]));
        mx1 = fmaxf(mx1, fmaxf(c[nb][2], c[nb][3]));
    }
    mx0 = fmaxf(mx0, __shfl_xor_sync(0xffffffffu, mx0, 1));
    mx0 = fmaxf(mx0, __shfl_xor_sync(0xffffffffu, mx0, 2));
    mx1 = fmaxf(mx1, __shfl_xor_sync(0xffffffffu, mx1, 1));
    mx1 = fmaxf(mx1, __shfl_xor_sync(0xffffffffu, mx1, 2));

    float es0 = 0.f, es1 = 0.f;
    #pragma unroll
    for (int nb = 0; nb < 16; ++nb) {
        c[nb][0] = __expf(c[nb][0] - mx0); es0 += c[nb][0];
        c[nb][1] = __expf(c[nb][1] - mx0); es0 += c[nb][1];
        c[nb][2] = __expf(c[nb][2] - mx1); es1 += c[nb][2];
        c[nb][3] = __expf(c[nb][3] - mx1); es1 += c[nb][3];
    }
    es0 += __shfl_xor_sync(0xffffffffu, es0, 1);
    es0 += __shfl_xor_sync(0xffffffffu, es0, 2);
    es1 += __shfl_xor_sync(0xffffffffu, es1, 1);
    es1 += __shfl_xor_sync(0xffffffffu, es1, 2);

    float* s0 = sc + ((size_t)bh * S + r0) * S + colb;
    float* s1 = sc + ((size_t)bh * S + r1) * S + colb;
    #pragma unroll
    for (int nb = 0; nb < 16; ++nb) {
        *(float2*)(s0 + nb * 8) = make_float2(c[nb][0], c[nb][1]);
        *(float2*)(s1 + nb * 8) = make_float2(c[nb][2], c[nb][3]);
    }
    if (tig == 0) {
        const size_t i0 = ((size_t)bh * 16 + kt) * S + r0;
        const size_t i1 = ((size_t)bh * 16 + kt) * S + r1;
        g_part[i0] = mx0; g_psum[i0] = es0;
        g_part[i1] = mx1; g_psum[i1] = es1;
    }
}

// ---------------- row stats: combine 16 tile partials -> rowmax + 1/rowsum ----------
__global__ void rowstat_kernel() {
    const int idx = blockIdx.x * 256 + threadIdx.x;   // 0..65535
    const int bh = idx >> 11, q = idx & 2047;
    float m = -INFINITY;
    #pragma unroll
    for (int kt = 0; kt < 16; ++kt)
        m = fmaxf(m, g_part[((size_t)bh * 16 + kt) * S + q]);
    float s = 0.f;
    #pragma unroll
    for (int kt = 0; kt < 16; ++kt) {
        const size_t i = ((size_t)bh * 16 + kt) * S + q;
        s += g_psum[i] * __expf(g_part[i] - m);
    }
    g_rowmax[idx] = m;
    g_rowinv[idx] = 1.0f / s;
}

// ---------------- k-partitioned normalize + PV via mma.sync TF32 ----------------
// grid (kt=32, qt=16, bh=32); block: 128q x 64k tile; 8 warps, warp = 16 q-rows.
// ctx accumulated via global atomics across kt.
__global__ __launch_bounds__(256, 3) void pv_mma_kernel(
        float* __restrict__ sc, const float* __restrict__ V,
        float* __restrict__ ctx, int writeAttn) {
    const int kt = blockIdx.x, qt = blockIdx.y, bh = blockIdx.z;
    const int b = bh >> 2, h = bh & 3;
    __shared__ float as[128][68];                 // attn row-major [q][k]; frag loads conflict-free
    __shared__ float vt[32][65];                  // V transposed [d][k]; stores conflict-free
    __shared__ float fac[128];                    // exp(tilemax - rowmax) / rowsum
    const int tid = threadIdx.x;
    const int w = tid >> 5, lane = tid & 31;
    const int gid = lane >> 2, tig = lane & 3;

    if (tid < 128) {
        const int q = qt * 128 + tid;
        const float mt = g_part[((size_t)bh * 16 + (kt >> 1)) * S + q];
        fac[tid] = __expf(mt - g_rowmax[bh * S + q]) * g_rowinv[bh * S + q];
    }
    __syncthreads();

    // load e tile [128q x 64k], scale to final attn, write back, stage (tf32) in smem
    for (int f = tid; f < 2048; f += 256) {       // 128 rows * 16 float4
        const int row = f >> 4, sg = (f & 15) * 4;
        const size_t gidx = (((size_t)bh * S + qt * 128 + row) * S + (size_t)kt * 64 + sg) >> 2;
        float4 x = ((const float4*)sc)[gidx];
        const float fv = fac[row];
        x.x *= fv; x.y *= fv; x.z *= fv; x.w *= fv;
        if (writeAttn) ((float4*)sc)[gidx] = x;
        as[row][sg + 0] = tf32r(x.x);
        as[row][sg + 1] = tf32r(x.y);
        as[row][sg + 2] = tf32r(x.z);
        as[row][sg + 3] = tf32r(x.w);
    }
    // load V tile [64k x 32d], store transposed (tf32)
    const float4* vb = (const float4*)(V + ((size_t)bh * S + (size_t)kt * 64) * DK);
    for (int f = tid; f < 512; f += 256) {
        const int k = f >> 3, d4 = (f & 7) * 4;
        const float4 v = vb[f];
        vt[d4 + 0][k] = tf32r(v.x);
        vt[d4 + 1][k] = tf32r(v.y);
        vt[d4 + 2][k] = tf32r(v.z);
        vt[d4 + 3][k] = tf32r(v.w);
    }
    __syncthreads();

    // warp w: rows tq..tq+15; C = attn[16x64] @ V[64x32]
    const int tq = w * 16;
    float c[4][4];
    #pragma unroll
    for (int nb = 0; nb < 4; ++nb) { c[nb][0]=0.f; c[nb][1]=0.f; c[nb][2]=0.f; c[nb][3]=0.f; }

    #pragma unroll
    for (int ksi = 0; ksi < 8; ++ksi) {
        const int k8 = ksi * 8;
        const uint32_t a0 = __float_as_uint(as[tq + gid    ][k8 + tig]);
        const uint32_t a1 = __float_as_uint(as[tq + gid + 8][k8 + tig]);
        const uint32_t a2 = __float_as_uint(as[tq + gid    ][k8 + tig + 4]);
        const uint32_t a3 = __float_as_uint(as[tq + gid + 8][k8 + tig + 4]);
        #pragma unroll
        for (int nb = 0; nb < 4; ++nb) {
            const uint32_t b0 = __float_as_uint(vt[nb * 8 + gid][k8 + tig]);
            const uint32_t b1 = __float_as_uint(vt[nb * 8 + gid][k8 + tig + 4]);
            asm volatile(
                "mma.sync.aligned.m16n8k8.row.col.f32.tf32.tf32.f32 "
                "{%0,%1,%2,%3}, {%4,%5,%6,%7}, {%8,%9}, {%0,%1,%2,%3};"
                : "+f"(c[nb][0]), "+f"(c[nb][1]), "+f"(c[nb][2]), "+f"(c[nb][3])
                : "r"(a0), "r"(a1), "r"(a2), "r"(a3), "r"(b0), "r"(b1));
        }
    }

    // C mapping (verified R15): c0:(gid, 2tig) c1:(gid, 2tig+1) c2:(gid+8, 2tig) c3:(gid+8, 2tig+1)
    const int q0 = qt * 128 + tq + gid, q1 = q0 + 8;
    #pragma unroll
    for (int nb = 0; nb < 4; ++nb) {
        const int d = h * DK + nb * 8 + 2 * tig;
        float* p0 = &ctx[((size_t)b * S + q0) * D + d];
        float* p1 = &ctx[((size_t)b * S + q1) * D + d];
        atomicAdd(p0,     c[nb][0]);
        atomicAdd(p0 + 1, c[nb][1]);
        atomicAdd(p1,     c[nb][2]);
        atomicAdd(p1 + 1, c[nb][3]);
    }
}

// ---------------- final: y = ctx @ Wo + resid; out = layernorm(y) ----------------
__global__ __launch_bounds__(128) void out_kernel(const float* __restrict__ Wo,
                                                  float* __restrict__ out) {
    __shared__ float xs[16][128];
    __shared__ float ys[16][129];
    __shared__ float mu[16], rstd[16];
    const int rowBase = blockIdx.x * 16;
    const int c = threadIdx.x;

    #pragma unroll
    for (int r = 0; r < 16; ++r)
        xs[r][c] = g_ctx[(size_t)(rowBase + r) * D + c];
    __syncthreads();

    float acc[16];
    #pragma unroll
    for (int r = 0; r < 16; ++r)
        acc[r] = g_resid[(size_t)(rowBase + r) * D + c];
    for (int k = 0; k < D; ++k) {
        float w = Wo[k * D + c];
        #pragma unroll
        for (int r = 0; r < 16; ++r)
            acc[r] = fmaf(xs[r][k], w, acc[r]);
    }
    #pragma unroll
    for (int r = 0; r < 16; ++r) ys[r][c] = acc[r];
    __syncthreads();

    if (c < 16) {
        float s1 = 0.f, s2 = 0.f;
        for (int k = 0; k < D; ++k) { float v = ys[c][k]; s1 += v; s2 += v * v; }
        const float m = s1 * (1.0f / D);
        const float var = s2 * (1.0f / D) - m * m;
        mu[c] = m; rstd[c] = rsqrtf(var + EPS);
    }
    __syncthreads();
    #pragma unroll
    for (int r = 0; r < 16; ++r)
        out[(size_t)(rowBase + r) * D + c] = (ys[r][c] - mu[r]) * rstd[r];
}

// ---------------- launch ----------------
extern "C" void kernel_launch(void* const* d_in, const int* in_sizes, int n_in,
                              void* d_out, int out_size) {
    const float* inQ = (const float*)d_in[0];
    const float* inK = (const float*)d_in[1];
    const float* inV = (const float*)d_in[2];
    const int*   mask = (const int*)d_in[3];      // bool stored as 4-byte (proven R7)
    const float* W0 = (const float*)d_in[4];
    const float* Wq = (const float*)d_in[5];
    const float* Wk = (const float*)d_in[6];
    const float* Wv = (const float*)d_in[7];
    const float* Wo = (const float*)d_in[8];
    float* out = (float*)d_out;

    float *resid_p, *Q_p, *K_p, *V_p, *ctx_p, *sc_p;
    cudaGetSymbolAddress((void**)&resid_p, g_resid);
    cudaGetSymbolAddress((void**)&Q_p, g_Q);
    cudaGetSymbolAddress((void**)&K_p, g_K);
    cudaGetSymbolAddress((void**)&V_p, g_V);
    cudaGetSymbolAddress((void**)&ctx_p, g_ctx);
    cudaGetSymbolAddress((void**)&sc_p, g_scores);

    const size_t normElems = (size_t)RT * D;                 // 2,097,152
    const size_t attnElems = (size_t)B * H * S * S;          // 134,217,728
    const int attnInOut = ((size_t)out_size >= normElems + attnElems);
    float* sc = attnInOut ? out + normElems : sc_p;

    // 0) zero the atomic-accumulated ctx
    zero_ctx_kernel<<<RT * D / 4 / 256, 256>>>(ctx_p);

    // 1) all projections, one launch
    proj_all_kernel<<<dim3(RT / 8, 4), 128>>>(inQ, inK, inV, W0, Wq, Wk, Wv,
                                              resid_p, Q_p, K_p, V_p);

    // 2) mma.sync TF32 QK^T -> e = exp(x - tilemax) + per-tile (max, expsum)
    scores_mma_kernel<<<dim3(16, 16, 32), 256>>>(Q_p, K_p, mask, sc);

    // 3) row stats (max + inverse sum)
    rowstat_kernel<<<256, 256>>>();

    // 4) k-partitioned normalize + attn write + PV on tensor pipe (atomic ctx)
    pv_mma_kernel<<<dim3(32, 16, 32), 256>>>(sc, V_p, ctx_p, attnInOut);

    // 5) output proj + residual + layernorm
    out_kernel<<<RT / 16, 128>>>(Wo, out);
}

// round 17
// speedup vs baseline: 1.9288x; 1.1322x over previous
#include <cuda_runtime.h>
#include <math.h>
#include <stdint.h>

#define B 8
#define S 2048
#define D 128
#define H 4
#define DK 32
#define RT (B*S)          // 16384 rows
#define EPS 1e-5f

// TF32 rounding for mma.sync input registers
__device__ __forceinline__ float tf32r(float x) {
    float y;
    asm("cvt.rna.tf32.f32 %0, %1;" : "=f"(y) : "f"(x));
    return y;
}

// ---------------- scratch (static __device__ globals; no allocation) ----------------
__device__ float g_resid[RT * D];                 // [B*S, D]
__device__ float g_Q[RT * D];                     // [B,H,S,DK]
__device__ float g_K[RT * D];                     // [B,H,S,DK]
__device__ float g_V[RT * D];                     // [B,H,S,DK]
__device__ float g_ctx[RT * D];                   // [B,S,H*DK]
__device__ float g_part[32 * 16 * S];             // per-(bh,ktile128,q) tile max
__device__ float g_psum[32 * 16 * S];             // per-(bh,ktile128,q) sum exp(x - tilemax)
__device__ float g_rowmax[32 * S];                // per-(bh,q) row max
__device__ float g_rowinv[32 * S];                // per-(bh,q) 1/rowsum
__device__ uint4 g_bmask[8192 * 8 * 16];          // ballot bitmask: tile*8*16 + w*16 + nb
__device__ float g_scores[134217728];             // [B,H,S,S] fallback if attn not in d_out

// ---------------- zero ctx (atomic accumulation target) ----------------
__global__ void zero_ctx_kernel(float* __restrict__ ctx) {
    const int i = blockIdx.x * 256 + threadIdx.x;
    ((float4*)ctx)[i] = make_float4(0.f, 0.f, 0.f, 0.f);
}

// ---------------- all 4 projections in one launch: blockIdx.y selects ----------------
__global__ __launch_bounds__(128) void proj_all_kernel(
        const float* __restrict__ inQ, const float* __restrict__ inK,
        const float* __restrict__ inV,
        const float* __restrict__ W0, const float* __restrict__ Wq,
        const float* __restrict__ Wk, const float* __restrict__ Wv,
        float* __restrict__ resid, float* __restrict__ Qo,
        float* __restrict__ Ko, float* __restrict__ Vo) {
    const float* X; const float* W; float* out; int headSplit;
    switch (blockIdx.y) {
        case 0: X = inQ; W = W0; out = resid; headSplit = 0; break;
        case 1: X = inQ; W = Wq; out = Qo;    headSplit = 1; break;
        case 2: X = inK; W = Wk; out = Ko;    headSplit = 1; break;
        default:X = inV; W = Wv; out = Vo;    headSplit = 1; break;
    }
    __shared__ float xs[8][128];
    const int rowBase = blockIdx.x * 8;
    const int c = threadIdx.x;
    #pragma unroll
    for (int r = 0; r < 8; ++r)
        xs[r][c] = X[(size_t)(rowBase + r) * D + c];
    __syncthreads();

    float acc[8];
    #pragma unroll
    for (int r = 0; r < 8; ++r) acc[r] = 0.f;
    for (int k = 0; k < D; ++k) {
        float w = W[k * D + c];
        #pragma unroll
        for (int r = 0; r < 8; ++r)
            acc[r] = fmaf(xs[r][k], w, acc[r]);
    }

    if (!headSplit) {
        #pragma unroll
        for (int r = 0; r < 8; ++r)
            out[(size_t)(rowBase + r) * D + c] = acc[r];
    } else {
        const int h = c >> 5, d = c & 31;
        #pragma unroll
        for (int r = 0; r < 8; ++r) {
            const int row = rowBase + r;
            const int b = row / S, s = row % S;
            out[(((size_t)(b * H + h)) * S + s) * DK + d] = acc[r];
        }
    }
}

// ---------------- Kernel A: QK^T stats only (no score store) + mask bitmask ----------
// grid (kt=16, qt=16, bh=32), 256 threads (8 warps). Warp = 16 q-rows x 128 k-cols.
__global__ __launch_bounds__(256, 2) void scores_stats_kernel(
        const float* __restrict__ Q, const float* __restrict__ K,
        const int* __restrict__ mask) {
    const int kt = blockIdx.x, qt = blockIdx.y, bh = blockIdx.z;
    const int b = bh >> 2;                        // bh = b*H + h
    __shared__ float qs[128][36];
    __shared__ float ks[128][36];
    const int tid = threadIdx.x;
    const int w = tid >> 5, lane = tid & 31;
    const int gid = lane >> 2, tig = lane & 3;

    const float4* Qb = (const float4*)(Q + ((size_t)bh * S + (size_t)qt * 128) * DK);
    const float4* Kb = (const float4*)(K + ((size_t)bh * S + (size_t)kt * 128) * DK);
    for (int f = tid; f < 1024; f += 256) {
        const int row = f >> 3, sg = (f & 7) * 4;
        float4 v = Qb[f];
        qs[row][sg] = tf32r(v.x); qs[row][sg+1] = tf32r(v.y);
        qs[row][sg+2] = tf32r(v.z); qs[row][sg+3] = tf32r(v.w);
        v = Kb[f];
        ks[row][sg] = tf32r(v.x); ks[row][sg+1] = tf32r(v.y);
        ks[row][sg+2] = tf32r(v.z); ks[row][sg+3] = tf32r(v.w);
    }
    __syncthreads();

    const int tq = w * 16;
    float c[16][4];
    #pragma unroll
    for (int nb = 0; nb < 16; ++nb) { c[nb][0]=0.f; c[nb][1]=0.f; c[nb][2]=0.f; c[nb][3]=0.f; }

    uint32_t a[4][4];
    #pragma unroll
    for (int ksi = 0; ksi < 4; ++ksi) {
        const int k8 = ksi * 8;
        a[ksi][0] = __float_as_uint(qs[tq + gid    ][k8 + tig]);
        a[ksi][1] = __float_as_uint(qs[tq + gid + 8][k8 + tig]);
        a[ksi][2] = __float_as_uint(qs[tq + gid    ][k8 + tig + 4]);
        a[ksi][3] = __float_as_uint(qs[tq + gid + 8][k8 + tig + 4]);
    }
    #pragma unroll
    for (int nb = 0; nb < 16; ++nb) {
        const int nrow = nb * 8 + gid;
        #pragma unroll
        for (int ksi = 0; ksi < 4; ++ksi) {
            const int k8 = ksi * 8;
            const uint32_t b0 = __float_as_uint(ks[nrow][k8 + tig]);
            const uint32_t b1 = __float_as_uint(ks[nrow][k8 + tig + 4]);
            asm volatile(
                "mma.sync.aligned.m16n8k8.row.col.f32.tf32.tf32.f32 "
                "{%0,%1,%2,%3}, {%4,%5,%6,%7}, {%8,%9}, {%0,%1,%2,%3};"
                : "+f"(c[nb][0]), "+f"(c[nb][1]), "+f"(c[nb][2]), "+f"(c[nb][3])
                : "r"(a[ksi][0]), "r"(a[ksi][1]), "r"(a[ksi][2]), "r"(a[ksi][3]),
                  "r"(b0), "r"(b1));
        }
    }

    const float scale = 0.17677669529663687f;     // 1/sqrt(32)
    const int r0 = qt * 128 + tq + gid, r1 = r0 + 8;
    const int colb = kt * 128 + 2 * tig;
    const int* mp0 = mask + ((size_t)b * S + r0) * S + colb;
    const int* mp1 = mask + ((size_t)b * S + r1) * S + colb;
    const size_t bmbase = (((size_t)((bh * 16 + qt) * 16 + kt)) * 8 + w) * 16;
    float mx0 = -INFINITY, mx1 = -INFINITY;
    #pragma unroll
    for (int nb = 0; nb < 16; ++nb) {
        const int2 m0 = *(const int2*)(mp0 + nb * 8);
        const int2 m1 = *(const int2*)(mp1 + nb * 8);
        const unsigned bb0 = __ballot_sync(0xffffffffu, m0.x != 0);
        const unsigned bb1 = __ballot_sync(0xffffffffu, m0.y != 0);
        const unsigned bb2 = __ballot_sync(0xffffffffu, m1.x != 0);
        const unsigned bb3 = __ballot_sync(0xffffffffu, m1.y != 0);
        if (lane == 0) g_bmask[bmbase + nb] = make_uint4(bb0, bb1, bb2, bb3);
        c[nb][0] = m0.x ? -1e9f : c[nb][0] * scale;
        c[nb][1] = m0.y ? -1e9f : c[nb][1] * scale;
        c[nb][2] = m1.x ? -1e9f : c[nb][2] * scale;
        c[nb][3] = m1.y ? -1e9f : c[nb][3] * scale;
        mx0 = fmaxf(mx0, fmaxf(c[nb][0], c[nb][1]));
        mx1 = fmaxf(mx1, fmaxf(c[nb][2], c[nb][3]));
    }
    mx0 = fmaxf(mx0, __shfl_xor_sync(0xffffffffu, mx0, 1));
    mx0 = fmaxf(mx0, __shfl_xor_sync(0xffffffffu, mx0, 2));
    mx1 = fmaxf(mx1, __shfl_xor_sync(0xffffffffu, mx1, 1));
    mx1 = fmaxf(mx1, __shfl_xor_sync(0xffffffffu, mx1, 2));

    float es0 = 0.f, es1 = 0.f;
    #pragma unroll
    for (int nb = 0; nb < 16; ++nb) {
        es0 += __expf(c[nb][0] - mx0) + __expf(c[nb][1] - mx0);
        es1 += __expf(c[nb][2] - mx1) + __expf(c[nb][3] - mx1);
    }
    es0 += __shfl_xor_sync(0xffffffffu, es0, 1);
    es0 += __shfl_xor_sync(0xffffffffu, es0, 2);
    es1 += __shfl_xor_sync(0xffffffffu, es1, 1);
    es1 += __shfl_xor_sync(0xffffffffu, es1, 2);

    if (tig == 0) {
        const size_t i0 = ((size_t)bh * 16 + kt) * S + r0;
        const size_t i1 = ((size_t)bh * 16 + kt) * S + r1;
        g_part[i0] = mx0; g_psum[i0] = es0;
        g_part[i1] = mx1; g_psum[i1] = es1;
    }
}

// ---------------- row stats: combine 16 tile partials -> rowmax + 1/rowsum ----------
__global__ void rowstat_kernel() {
    const int idx = blockIdx.x * 256 + threadIdx.x;   // 0..65535
    const int bh = idx >> 11, q = idx & 2047;
    float m = -INFINITY;
    #pragma unroll
    for (int kt = 0; kt < 16; ++kt)
        m = fmaxf(m, g_part[((size_t)bh * 16 + kt) * S + q]);
    float s = 0.f;
    #pragma unroll
    for (int kt = 0; kt < 16; ++kt) {
        const size_t i = ((size_t)bh * 16 + kt) * S + q;
        s += g_psum[i] * __expf(g_part[i] - m);
    }
    g_rowmax[idx] = m;
    g_rowinv[idx] = 1.0f / s;
}

// ---------------- Kernel B: recompute QK^T, final attn write, PV on tensor pipe ------
// grid (kt=16, qt=16, bh=32), 256 threads, dynamic smem.
__global__ __launch_bounds__(256, 2) void attn_pv_kernel(
        const float* __restrict__ Q, const float* __restrict__ K,
        const float* __restrict__ V, float* __restrict__ sc,
        float* __restrict__ ctx, int writeAttn) {
    const int kt = blockIdx.x, qt = blockIdx.y, bh = blockIdx.z;
    const int b = bh >> 2, h = bh & 3;
    extern __shared__ float sm[];
    float* qs    = sm;                    // [128][36]
    float* ks    = qs + 128 * 36;         // [128][36]
    float* as_st = ks + 128 * 36;         // [128][68] attn half-tile staging
    float* vt    = as_st + 128 * 68;      // [32][132] V transposed
    const int tid = threadIdx.x;
    const int w = tid >> 5, lane = tid & 31;
    const int gid = lane >> 2, tig = lane & 3;

    // loads
    const float4* Qb = (const float4*)(Q + ((size_t)bh * S + (size_t)qt * 128) * DK);
    const float4* Kb = (const float4*)(K + ((size_t)bh * S + (size_t)kt * 128) * DK);
    for (int f = tid; f < 1024; f += 256) {
        const int row = f >> 3, sg = (f & 7) * 4;
        float4 v = Qb[f];
        qs[row * 36 + sg]     = tf32r(v.x); qs[row * 36 + sg + 1] = tf32r(v.y);
        qs[row * 36 + sg + 2] = tf32r(v.z); qs[row * 36 + sg + 3] = tf32r(v.w);
        v = Kb[f];
        ks[row * 36 + sg]     = tf32r(v.x); ks[row * 36 + sg + 1] = tf32r(v.y);
        ks[row * 36 + sg + 2] = tf32r(v.z); ks[row * 36 + sg + 3] = tf32r(v.w);
    }
    const float4* vb = (const float4*)(V + ((size_t)bh * S + (size_t)kt * 128) * DK);
    for (int f = tid; f < 1024; f += 256) {   // 128 k-rows * 8 float4
        const int k = f >> 3, d4 = (f & 7) * 4;
        const float4 v = vb[f];
        vt[(d4 + 0) * 132 + k] = tf32r(v.x);
        vt[(d4 + 1) * 132 + k] = tf32r(v.y);
        vt[(d4 + 2) * 132 + k] = tf32r(v.z);
        vt[(d4 + 3) * 132 + k] = tf32r(v.w);
    }
    __syncthreads();

    // QK^T MMA (identical to kernel A -> bit-identical x)
    const int tq = w * 16;
    float c[16][4];
    #pragma unroll
    for (int nb = 0; nb < 16; ++nb) { c[nb][0]=0.f; c[nb][1]=0.f; c[nb][2]=0.f; c[nb][3]=0.f; }
    uint32_t a[4][4];
    #pragma unroll
    for (int ksi = 0; ksi < 4; ++ksi) {
        const int k8 = ksi * 8;
        a[ksi][0] = __float_as_uint(qs[(tq + gid)     * 36 + k8 + tig]);
        a[ksi][1] = __float_as_uint(qs[(tq + gid + 8) * 36 + k8 + tig]);
        a[ksi][2] = __float_as_uint(qs[(tq + gid)     * 36 + k8 + tig + 4]);
        a[ksi][3] = __float_as_uint(qs[(tq + gid + 8) * 36 + k8 + tig + 4]);
    }
    #pragma unroll
    for (int nb = 0; nb < 16; ++nb) {
        const int nrow = nb * 8 + gid;
        #pragma unroll
        for (int ksi = 0; ksi < 4; ++ksi) {
            const int k8 = ksi * 8;
            const uint32_t b0 = __float_as_uint(ks[nrow * 36 + k8 + tig]);
            const uint32_t b1 = __float_as_uint(ks[nrow * 36 + k8 + tig + 4]);
            asm volatile(
                "mma.sync.aligned.m16n8k8.row.col.f32.tf32.tf32.f32 "
                "{%0,%1,%2,%3}, {%4,%5,%6,%7}, {%8,%9}, {%0,%1,%2,%3};"
                : "+f"(c[nb][0]), "+f"(c[nb][1]), "+f"(c[nb][2]), "+f"(c[nb][3])
                : "r"(a[ksi][0]), "r"(a[ksi][1]), "r"(a[ksi][2]), "r"(a[ksi][3]),
                  "r"(b0), "r"(b1));
        }
    }

    // final attn = bitmask ? 0 : exp(x*scale - m_row) * inv_row; write to gmem
    const float scale = 0.17677669529663687f;
    const int r0 = qt * 128 + tq + gid, r1 = r0 + 8;
    const float m0r = g_rowmax[bh * S + r0], iv0 = g_rowinv[bh * S + r0];
    const float m1r = g_rowmax[bh * S + r1], iv1 = g_rowinv[bh * S + r1];
    const size_t bmbase = (((size_t)((bh * 16 + qt) * 16 + kt)) * 8 + w) * 16;
    const int colb = kt * 128 + 2 * tig;
    float* s0 = sc + ((size_t)bh * S + r0) * S + colb;
    float* s1 = sc + ((size_t)bh * S + r1) * S + colb;
    #pragma unroll
    for (int nb = 0; nb < 16; ++nb) {
        const uint4 bb = g_bmask[bmbase + nb];
        c[nb][0] = ((bb.x >> lane) & 1u) ? 0.f : __expf(fmaf(c[nb][0], scale, -m0r)) * iv0;
        c[nb][1] = ((bb.y >> lane) & 1u) ? 0.f : __expf(fmaf(c[nb][1], scale, -m0r)) * iv0;
        c[nb][2] = ((bb.z >> lane) & 1u) ? 0.f : __expf(fmaf(c[nb][2], scale, -m1r)) * iv1;
        c[nb][3] = ((bb.w >> lane) & 1u) ? 0.f : __expf(fmaf(c[nb][3], scale, -m1r)) * iv1;
        if (writeAttn) {
            *(float2*)(s0 + nb * 8) = make_float2(c[nb][0], c[nb][1]);
            *(float2*)(s1 + nb * 8) = make_float2(c[nb][2], c[nb][3]);
        }
    }

    // PV: two 64-k halves staged through smem; accumulate C[16q x 32d] per warp
    float cpv[4][4];
    #pragma unroll
    for (int nb = 0; nb < 4; ++nb) { cpv[nb][0]=0.f; cpv[nb][1]=0.f; cpv[nb][2]=0.f; cpv[nb][3]=0.f; }

    #pragma unroll
    for (int half = 0; half < 2; ++half) {
        __syncthreads();                        // qs/ks (half0) or as_st (half1) free
        #pragma unroll
        for (int nbl = 0; nbl < 8; ++nbl) {
            const int nb = half * 8 + nbl;
            *(float2*)&as_st[(tq + gid)     * 68 + nbl * 8 + 2 * tig] =
                make_float2(tf32r(c[nb][0]), tf32r(c[nb][1]));
            *(float2*)&as_st[(tq + gid + 8) * 68 + nbl * 8 + 2 * tig] =
                make_float2(tf32r(c[nb][2]), tf32r(c[nb][3]));
        }
        __syncthreads();
        #pragma unroll
        for (int ksi = 0; ksi < 8; ++ksi) {
            const int k8 = ksi * 8;
            const uint32_t a0 = __float_as_uint(as_st[(tq + gid)     * 68 + k8 + tig]);
            const uint32_t a1 = __float_as_uint(as_st[(tq + gid + 8) * 68 + k8 + tig]);
            const uint32_t a2 = __float_as_uint(as_st[(tq + gid)     * 68 + k8 + tig + 4]);
            const uint32_t a3 = __float_as_uint(as_st[(tq + gid + 8) * 68 + k8 + tig + 4]);
            #pragma unroll
            for (int nbd = 0; nbd < 4; ++nbd) {
                const uint32_t b0 = __float_as_uint(vt[(nbd * 8 + gid) * 132 + half * 64 + k8 + tig]);
                const uint32_t b1 = __float_as_uint(vt[(nbd * 8 + gid) * 132 + half * 64 + k8 + tig + 4]);
                asm volatile(
                    "mma.sync.aligned.m16n8k8.row.col.f32.tf32.tf32.f32 "
                    "{%0,%1,%2,%3}, {%4,%5,%6,%7}, {%8,%9}, {%0,%1,%2,%3};"
                    : "+f"(cpv[nbd][0]), "+f"(cpv[nbd][1]), "+f"(cpv[nbd][2]), "+f"(cpv[nbd][3])
                    : "r"(a0), "r"(a1), "r"(a2), "r"(a3), "r"(b0), "r"(b1));
            }
        }
    }

    // C mapping: c0:(gid,2tig) c1:(gid,2tig+1) c2:(gid+8,2tig) c3:(gid+8,2tig+1)
    #pragma unroll
    for (int nbd = 0; nbd < 4; ++nbd) {
        const int d = h * DK + nbd * 8 + 2 * tig;
        float* p0 = &ctx[((size_t)b * S + r0) * D + d];
        float* p1 = &ctx[((size_t)b * S + r1) * D + d];
        atomicAdd(p0,     cpv[nbd][0]);
        atomicAdd(p0 + 1, cpv[nbd][1]);
        atomicAdd(p1,     cpv[nbd][2]);
        atomicAdd(p1 + 1, cpv[nbd][3]);
    }
}

// ---------------- final: y = ctx @ Wo + resid; out = layernorm(y) ----------------
__global__ __launch_bounds__(128) void out_kernel(const float* __restrict__ Wo,
                                                  float* __restrict__ out) {
    __shared__ float xs[16][128];
    __shared__ float ys[16][129];
    __shared__ float mu[16], rstd[16];
    const int rowBase = blockIdx.x * 16;
    const int c = threadIdx.x;

    #pragma unroll
    for (int r = 0; r < 16; ++r)
        xs[r][c] = g_ctx[(size_t)(rowBase + r) * D + c];
    __syncthreads();

    float acc[16];
    #pragma unroll
    for (int r = 0; r < 16; ++r)
        acc[r] = g_resid[(size_t)(rowBase + r) * D + c];
    for (int k = 0; k < D; ++k) {
        float w = Wo[k * D + c];
        #pragma unroll
        for (int r = 0; r < 16; ++r)
            acc[r] = fmaf(xs[r][k], w, acc[r]);
    }
    #pragma unroll
    for (int r = 0; r < 16; ++r) ys[r][c] = acc[r];
    __syncthreads();

    if (c < 16) {
        float s1 = 0.f, s2 = 0.f;
        for (int k = 0; k < D; ++k) { float v = ys[c][k]; s1 += v; s2 += v * v; }
        const float m = s1 * (1.0f / D);
        const float var = s2 * (1.0f / D) - m * m;
        mu[c] = m; rstd[c] = rsqrtf(var + EPS);
    }
    __syncthreads();
    #pragma unroll
    for (int r = 0; r < 16; ++r)
        out[(size_t)(rowBase + r) * D + c] = (ys[r][c] - mu[r]) * rstd[r];
}

// ---------------- launch ----------------
extern "C" void kernel_launch(void* const* d_in, const int* in_sizes, int n_in,
                              void* d_out, int out_size) {
    const float* inQ = (const float*)d_in[0];
    const float* inK = (const float*)d_in[1];
    const float* inV = (const float*)d_in[2];
    const int*   mask = (const int*)d_in[3];      // bool stored as 4-byte (proven R7)
    const float* W0 = (const float*)d_in[4];
    const float* Wq = (const float*)d_in[5];
    const float* Wk = (const float*)d_in[6];
    const float* Wv = (const float*)d_in[7];
    const float* Wo = (const float*)d_in[8];
    float* out = (float*)d_out;

    float *resid_p, *Q_p, *K_p, *V_p, *ctx_p, *sc_p;
    cudaGetSymbolAddress((void**)&resid_p, g_resid);
    cudaGetSymbolAddress((void**)&Q_p, g_Q);
    cudaGetSymbolAddress((void**)&K_p, g_K);
    cudaGetSymbolAddress((void**)&V_p, g_V);
    cudaGetSymbolAddress((void**)&ctx_p, g_ctx);
    cudaGetSymbolAddress((void**)&sc_p, g_scores);

    const size_t normElems = (size_t)RT * D;                 // 2,097,152
    const size_t attnElems = (size_t)B * H * S * S;          // 134,217,728
    const int attnInOut = ((size_t)out_size >= normElems + attnElems);
    float* sc = attnInOut ? out + normElems : sc_p;

    // dynamic smem for attn_pv_kernel: (128*36*2 + 128*68 + 32*132) floats = 88,576 B
    const int SMEM_B_BYTES = (128 * 36 * 2 + 128 * 68 + 32 * 132) * 4;
    cudaFuncSetAttribute(attn_pv_kernel, cudaFuncAttributeMaxDynamicSharedMemorySize,
                         SMEM_B_BYTES);

    // 0) zero the atomic-accumulated ctx
    zero_ctx_kernel<<<RT * D / 4 / 256, 256>>>(ctx_p);

    // 1) all projections, one launch
    proj_all_kernel<<<dim3(RT / 8, 4), 128>>>(inQ, inK, inV, W0, Wq, Wk, Wv,
                                              resid_p, Q_p, K_p, V_p);

    // 2) QK^T stats + mask bitmask (no 536MB intermediate write)
    scores_stats_kernel<<<dim3(16, 16, 32), 256>>>(Q_p, K_p, mask);

    // 3) row stats (max + inverse sum)
    rowstat_kernel<<<256, 256>>>();

    // 4) recompute QK^T, write final attn, PV on tensor pipe (atomic ctx)
    attn_pv_kernel<<<dim3(16, 16, 32), 256, SMEM_B_BYTES>>>(Q_p, K_p, V_p, sc,
                                                            ctx_p, attnInOut);

    // 5) output proj + residual + layernorm
    out_kernel<<<RT / 16, 128>>>(Wo, out);
}